// round 11
// baseline (speedup 1.0000x reference)
#include <cuda_runtime.h>
#include <cuda_bf16.h>
#include <cuda_fp16.h>

#define NMAX 100000
#define EMAX 1600000
#define MASKV (-1000000000.0f)
#define INV_TAU 2.0f

// ---------------- device scratch (static allocation only) ----------------
struct Scr {
    float poolsum[128];
    unsigned int poolmax[128];
    float zmax[2];
    float S[2];
    int isel[2];
};

__device__ __half d_H[NMAX * 128];   // GEMM output (pre-aggregation)
__device__ __half d_P[NMAX * 128];   // activation ping
__device__ __half d_Q[NMAX * 128];   // activation pong
__device__ int    d_counts[NMAX];
__device__ int    d_rowstart[NMAX + 1];
__device__ int    d_cursor[NMAX];
__device__ int    d_csr[EMAX];
__device__ float  d_dinv[NMAX];
__device__ float  d_z1[NMAX];
__device__ float  d_l2[NMAX];
__device__ float  d_z2[NMAX];
__device__ unsigned char d_conn[NMAX];
__device__ int    d_bsum[128];
__device__ int    d_boff[128];
__device__ float  d_bm[2][128];
__device__ float  d_bs[2][128];
__device__ unsigned long long d_bk[2][128];
__device__ Scr    d_scr;

// ---------------- CSR build ----------------
__global__ void degcount_k(const int* __restrict__ dstp, int E) {
    int e = blockIdx.x * blockDim.x + threadIdx.x;
    if (e < E) atomicAdd(&d_counts[dstp[e]], 1);
}

__global__ void scan1_k(int n) {
    __shared__ int sm[1024];
    int t = threadIdx.x;
    int i = blockIdx.x * 1024 + t;
    int v = (i < n) ? d_counts[i] : 0;
    sm[t] = v;
    __syncthreads();
    for (int s = 512; s > 0; s >>= 1) {
        if (t < s) sm[t] += sm[t + s];
        __syncthreads();
    }
    if (t == 0) d_bsum[blockIdx.x] = sm[0];
}

__global__ void scan2_k(int nb, int n) {
    __shared__ int sm[128];
    int t = threadIdx.x;
    int v = (t < nb) ? d_bsum[t] : 0;
    sm[t] = v;
    __syncthreads();
    for (int d = 1; d < 128; d <<= 1) {
        int add = (t >= d) ? sm[t - d] : 0;
        __syncthreads();
        sm[t] += add;
        __syncthreads();
    }
    if (t < nb) d_boff[t] = sm[t] - v;
    if (t == nb - 1) d_rowstart[n] = sm[t];
}

__global__ void scan3_k(int n) {
    __shared__ int sm[1024];
    int t = threadIdx.x;
    int i = blockIdx.x * 1024 + t;
    int v = (i < n) ? d_counts[i] : 0;
    sm[t] = v;
    __syncthreads();
    for (int d = 1; d < 1024; d <<= 1) {
        int add = (t >= d) ? sm[t - d] : 0;
        __syncthreads();
        sm[t] += add;
        __syncthreads();
    }
    if (i < n) {
        int excl = sm[t] - v + d_boff[blockIdx.x];
        d_rowstart[i] = excl;
        d_cursor[i]   = excl;
        d_dinv[i]     = rsqrtf((float)v + 1.0f);
    }
}

__global__ void fill_csr_k(const int* __restrict__ srcp, const int* __restrict__ dstp, int E) {
    int e = blockIdx.x * blockDim.x + threadIdx.x;
    if (e < E) {
        int d = dstp[e];
        int pos = atomicAdd(&d_cursor[d], 1);
        d_csr[pos] = srcp[e];
    }
}

// ---------------- fp16 tensor-core GEMM: Hout = fp16(dinv * (X @ W)) ------
// xf32 != 0: X32 is the fp32 input (layer 1, converts during smem store).
#define XS_H 136
#define BS_W 132

__device__ __forceinline__ void mma_f16(float* d,
                                        unsigned a0, unsigned a1, unsigned a2, unsigned a3,
                                        unsigned b0, unsigned b1) {
    asm volatile("mma.sync.aligned.m16n8k16.row.col.f32.f16.f16.f32 "
                 "{%0,%1,%2,%3}, {%4,%5,%6,%7}, {%8,%9}, {%0,%1,%2,%3};"
                 : "+f"(d[0]), "+f"(d[1]), "+f"(d[2]), "+f"(d[3])
                 : "r"(a0), "r"(a1), "r"(a2), "r"(a3), "r"(b0), "r"(b1));
}

__global__ __launch_bounds__(256) void gemm_f16_k(const __half* __restrict__ X,
                                                  const float* __restrict__ X32,
                                                  int xf32,
                                                  const float* __restrict__ W,
                                                  __half* __restrict__ Hout, int n) {
    extern __shared__ char shraw[];
    __half*  xs = (__half*)shraw;                    // 64 x XS_H halfs
    __half2* bs = (__half2*)(shraw + 64 * XS_H * 2); // 64 x BS_W half2 (k-pairs)

    int t = threadIdx.x;
    int row0 = blockIdx.x * 64;
    int nr = n - row0; if (nr > 64) nr = 64;

    for (int i = t; i < 64 * 128; i += 256) {
        int k2 = i >> 7, nn = i & 127;
        float w0 = W[(size_t)(2 * k2) * 128 + nn];
        float w1 = W[(size_t)(2 * k2 + 1) * 128 + nn];
        bs[k2 * BS_W + nn] = __floats2half2_rn(w0, w1);
    }
    if (xf32) {
        // fp32 rows -> fp16 smem (identical rounding to a separate cvt pass)
        for (int i = t; i < nr * 32; i += 256) {
            int rr = i >> 5, c4 = i & 31;
            float4 v = *(const float4*)(X32 + (size_t)(row0 + rr) * 128 + c4 * 4);
            __half2 a = __floats2half2_rn(v.x, v.y);
            __half2 b = __floats2half2_rn(v.z, v.w);
            *(uint2*)(xs + rr * XS_H + c4 * 4) = make_uint2(*(unsigned*)&a, *(unsigned*)&b);
        }
    } else {
        for (int i = t; i < nr * 16; i += 256) {
            int rr = i >> 4, c8 = i & 15;
            uint4 v = *(const uint4*)(X + (size_t)(row0 + rr) * 128 + c8 * 8);
            *(uint4*)(xs + rr * XS_H + c8 * 8) = v;
        }
    }
    __syncthreads();

    int lane = t & 31, wid = t >> 5;
    int wm = wid & 1, wn = wid >> 1;
    int m0 = wm * 32, n0 = wn * 32;
    int r = lane >> 2, c = lane & 3;

    float acc[2][4][4];
#pragma unroll
    for (int mi = 0; mi < 2; mi++)
#pragma unroll
        for (int nj = 0; nj < 4; nj++)
#pragma unroll
            for (int q = 0; q < 4; q++) acc[mi][nj][q] = 0.f;

#pragma unroll
    for (int k0 = 0; k0 < 8; k0++) {
        unsigned a[2][4];
#pragma unroll
        for (int mi = 0; mi < 2; mi++) {
            const __half* xb = xs + (m0 + mi * 16 + r) * XS_H + k0 * 16 + 2 * c;
            a[mi][0] = *(const unsigned*)(xb);
            a[mi][1] = *(const unsigned*)(xb + 8 * XS_H);
            a[mi][2] = *(const unsigned*)(xb + 8);
            a[mi][3] = *(const unsigned*)(xb + 8 * XS_H + 8);
        }
#pragma unroll
        for (int nj = 0; nj < 4; nj++) {
            const __half2* bb = bs + (k0 * 8 + c) * BS_W + n0 + nj * 8 + r;
            unsigned b0 = *(const unsigned*)(bb);
            unsigned b1 = *(const unsigned*)(bb + 4 * BS_W);
#pragma unroll
            for (int mi = 0; mi < 2; mi++)
                mma_f16(acc[mi][nj], a[mi][0], a[mi][1], a[mi][2], a[mi][3], b0, b1);
        }
    }

#pragma unroll
    for (int mi = 0; mi < 2; mi++) {
        int rloc = m0 + mi * 16 + r;
        float s0 = 0.f, s1 = 0.f;
        if (rloc < nr)     s0 = d_dinv[row0 + rloc];
        if (rloc + 8 < nr) s1 = d_dinv[row0 + rloc + 8];
#pragma unroll
        for (int nj = 0; nj < 4; nj++) {
            int col = n0 + nj * 8 + 2 * c;
            if (rloc < nr) {
                __half2 h = __floats2half2_rn(acc[mi][nj][0] * s0, acc[mi][nj][1] * s0);
                *(__half2*)(Hout + (size_t)(row0 + rloc) * 128 + col) = h;
            }
            if (rloc + 8 < nr) {
                __half2 h = __floats2half2_rn(acc[mi][nj][2] * s1, acc[mi][nj][3] * s1);
                *(__half2*)(Hout + (size_t)(row0 + rloc + 8) * 128 + col) = h;
            }
        }
    }
}

// ---------------- aggregation: half-warp per node, 8-deep gather pipeline --
// out_i = fp16( relu(dinv_i * (sum_{e:dst=i} H'[src] + H'[i]) + b) )
__global__ __launch_bounds__(256) void aggregate_k(const __half* __restrict__ H,
                                                   const float* __restrict__ bias,
                                                   __half* __restrict__ outp, int n,
                                                   int dopool) {
    __shared__ float pS[16][128];
    __shared__ float pM[16][128];
    int t = threadIdx.x;
    int hw = t >> 4;          // half-warp id in block, 0..15
    int lane16 = t & 15;
    int w = blockIdx.x * 16 + hw;
    unsigned hmask = 0xFFFFu << (t & 16);   // this half-warp's lanes only

    float o[8];
#pragma unroll
    for (int q = 0; q < 8; q++) o[q] = 0.f;

    if (w < n) {
        float acc[8];
#pragma unroll
        for (int q = 0; q < 8; q++) acc[q] = 0.f;
        int beg = d_rowstart[w];
        int end = d_rowstart[w + 1];
        const __half* Hl = H + lane16 * 8;
        for (int base = beg; base < end; base += 16) {
            int rem = end - base;
            int cnt = rem < 16 ? rem : 16;
            int idx = (lane16 < cnt) ? d_csr[base + lane16] : 0;
            uint4 h[8];
            int m0 = cnt < 8 ? cnt : 8;
#pragma unroll
            for (int u = 0; u < 8; u++) {
                if (u < m0) {
                    int s = __shfl_sync(hmask, idx, u, 16);
                    h[u] = *(const uint4*)(Hl + (size_t)s * 128);
                }
            }
            for (int j0 = 0; j0 < cnt; j0 += 8) {
                int curm = cnt - j0; if (curm > 8) curm = 8;
                int nxtm = cnt - j0 - 8;
                if (nxtm < 0) nxtm = 0;
                if (nxtm > 8) nxtm = 8;
                uint4 h2[8];
#pragma unroll
                for (int u = 0; u < 8; u++) {
                    if (u < nxtm) {
                        int s = __shfl_sync(hmask, idx, j0 + 8 + u, 16);
                        h2[u] = *(const uint4*)(Hl + (size_t)s * 128);
                    } else {
                        h2[u] = make_uint4(0u, 0u, 0u, 0u);
                    }
                }
#pragma unroll
                for (int u = 0; u < 8; u++) {
                    if (u < curm) {
                        const __half2* p2 = (const __half2*)&h[u];
#pragma unroll
                        for (int q = 0; q < 4; q++) {
                            float2 f = __half22float2(p2[q]);
                            acc[2 * q]     += f.x;
                            acc[2 * q + 1] += f.y;
                        }
                    }
                }
#pragma unroll
                for (int u = 0; u < 8; u++) h[u] = h2[u];
            }
        }
        // self-loop
        {
            uint4 hs = *(const uint4*)(Hl + (size_t)w * 128);
            const __half2* p2 = (const __half2*)&hs;
#pragma unroll
            for (int q = 0; q < 4; q++) {
                float2 f = __half22float2(p2[q]);
                acc[2 * q]     += f.x;
                acc[2 * q + 1] += f.y;
            }
        }
        float di = d_dinv[w];
        float4 b0 = *(const float4*)(bias + lane16 * 8);
        float4 b1 = *(const float4*)(bias + lane16 * 8 + 4);
        o[0] = fmaxf(di * acc[0] + b0.x, 0.f);
        o[1] = fmaxf(di * acc[1] + b0.y, 0.f);
        o[2] = fmaxf(di * acc[2] + b0.z, 0.f);
        o[3] = fmaxf(di * acc[3] + b0.w, 0.f);
        o[4] = fmaxf(di * acc[4] + b1.x, 0.f);
        o[5] = fmaxf(di * acc[5] + b1.y, 0.f);
        o[6] = fmaxf(di * acc[6] + b1.z, 0.f);
        o[7] = fmaxf(di * acc[7] + b1.w, 0.f);
        __half2 ho[4];
#pragma unroll
        for (int q = 0; q < 4; q++) ho[q] = __floats2half2_rn(o[2 * q], o[2 * q + 1]);
        *(uint4*)(outp + (size_t)w * 128 + lane16 * 8) = *(uint4*)ho;
    }

    if (dopool) {
#pragma unroll
        for (int q = 0; q < 8; q++) {
            pS[hw][lane16 * 8 + q] = o[q];
            pM[hw][lane16 * 8 + q] = o[q];
        }
        __syncthreads();
        if (t < 128) {
            float s = 0.f, mx = 0.f;
#pragma unroll
            for (int u = 0; u < 16; u++) { s += pS[u][t]; mx = fmaxf(mx, pM[u][t]); }
            atomicAdd(&d_scr.poolsum[t], s);
            atomicMax(&d_scr.poolmax[t], __float_as_uint(mx));
        }
    }
}

// ---------------- argmax key helpers ----------------
__device__ __forceinline__ unsigned enc_f(float f) {
    unsigned u = __float_as_uint(f);
    return (u & 0x80000000u) ? ~u : (u | 0x80000000u);
}
__device__ __forceinline__ unsigned long long mkkey(float f, int j) {
    return ((unsigned long long)enc_f(f) << 32) | (unsigned long long)(0xFFFFFFFFu - (unsigned)j);
}

// ---------------- head GEMVs + inline pool final + z1 block stats ----------
__global__ __launch_bounds__(256) void gemv_heads_k(const float* __restrict__ n1W,
                                                    const float* __restrict__ n1b,
                                                    const float* __restrict__ g1,
                                                    const float* __restrict__ n2W,
                                                    const float* __restrict__ n2b,
                                                    int ncols, int halfblocks, float inv_n) {
    __shared__ float p[256];
    __shared__ float red[256];
    __shared__ unsigned long long redk[256];
    int t = threadIdx.x;
    if (t < 128) p[t] = d_scr.poolsum[t] * inv_n;
    else         p[t] = __uint_as_float(d_scr.poolmax[t - 128]);
    __syncthreads();
    int second = blockIdx.x >= halfblocks;
    int b = second ? blockIdx.x - halfblocks : blockIdx.x;
    int j4 = b * blockDim.x + t;
    bool valid = (j4 * 4 < ncols);
    float ax = 0.f, ay = 0.f, az = 0.f, aw = 0.f;
    if (valid) {
        const float* W = second ? n2W : n1W;
#pragma unroll 4
        for (int k = 0; k < 256; k++) {
            float4 w4 = *(const float4*)(W + (size_t)k * ncols + j4 * 4);
            float pv = p[k];
            ax += pv * w4.x; ay += pv * w4.y; az += pv * w4.z; aw += pv * w4.w;
        }
    }
    int j = j4 * 4;
    if (!second) {
        float4 o = make_float4(0.f, 0.f, 0.f, 0.f);
        if (valid) {
            float4 bb = *(const float4*)(n1b + j);
            float4 gg = *(const float4*)(g1 + j);
            o.x = (ax + bb.x + gg.x) * INV_TAU;
            o.y = (ay + bb.y + gg.y) * INV_TAU;
            o.z = (az + bb.z + gg.z) * INV_TAU;
            o.w = (aw + bb.w + gg.w) * INV_TAU;
            *(float4*)(d_z1 + j) = o;
        }
        float lm = valid ? fmaxf(fmaxf(o.x, o.y), fmaxf(o.z, o.w)) : -1e30f;
        red[t] = lm;
        __syncthreads();
        for (int s = 128; s > 0; s >>= 1) {
            if (t < s) red[t] = fmaxf(red[t], red[t + s]);
            __syncthreads();
        }
        float bm = red[0];
        __syncthreads();
        float ls = 0.f;
        if (valid) {
            ls = expf(o.x - bm) + expf(o.y - bm) + expf(o.z - bm) + expf(o.w - bm);
        }
        red[t] = ls;
        unsigned long long key = 0ull;
        if (valid) {
            key = mkkey(o.x, j);
            unsigned long long k1 = mkkey(o.y, j + 1); if (k1 > key) key = k1;
            unsigned long long k2 = mkkey(o.z, j + 2); if (k2 > key) key = k2;
            unsigned long long k3 = mkkey(o.w, j + 3); if (k3 > key) key = k3;
        }
        redk[t] = key;
        __syncthreads();
        for (int s = 128; s > 0; s >>= 1) {
            if (t < s) {
                red[t] += red[t + s];
                if (redk[t + s] > redk[t]) redk[t] = redk[t + s];
            }
            __syncthreads();
        }
        if (t == 0) {
            d_bm[0][b] = bm;
            d_bs[0][b] = red[0];
            d_bk[0][b] = redk[0];
        }
    } else {
        if (valid) {
            float4 bb = *(const float4*)(n2b + j);
            float4 o;
            o.x = ax + bb.x; o.y = ay + bb.y; o.z = az + bb.z; o.w = aw + bb.w;
            *(float4*)(d_l2 + j) = o;
        }
    }
}

// ---------------- merge block stats -> global M, S, argmax ----------------
__global__ void merge_k(int which, int nb) {
    __shared__ float sm[128];
    __shared__ float ss[128];
    __shared__ unsigned long long sk[128];
    int t = threadIdx.x;  // 128
    float m = (t < nb) ? d_bm[which][t] : -1e30f;
    sm[t] = m;
    __syncthreads();
    for (int s = 64; s > 0; s >>= 1) {
        if (t < s) sm[t] = fmaxf(sm[t], sm[t + s]);
        __syncthreads();
    }
    float M = sm[0];
    __syncthreads();
    float ls = (t < nb) ? d_bs[which][t] * expf(d_bm[which][t] - M) : 0.f;
    ss[t] = ls;
    sk[t] = (t < nb) ? d_bk[which][t] : 0ull;
    __syncthreads();
    for (int s = 64; s > 0; s >>= 1) {
        if (t < s) {
            ss[t] += ss[t + s];
            if (sk[t + s] > sk[t]) sk[t] = sk[t + s];
        }
        __syncthreads();
    }
    if (t == 0) {
        d_scr.zmax[which] = M;
        d_scr.S[which] = ss[0];
        int idx = (int)(0xFFFFFFFFu - (unsigned)(sk[0] & 0xFFFFFFFFull));
        d_scr.isel[which] = idx;
        if (which == 0) d_conn[idx] = 1;
    }
}

// ---------------- mask of nodes connected to i1 ----------------
__global__ void conn_k(const int* __restrict__ srcp, const int* __restrict__ dstp, int E) {
    int i1 = d_scr.isel[0];
    int e = blockIdx.x * blockDim.x + threadIdx.x;
    if (e < E) {
        int s = srcp[e], d = dstp[e];
        if (s == i1 || d == i1) { d_conn[s] = 1; d_conn[d] = 1; }
    }
}

// ---------------- fused A: [write n1_soft] || [z2 compute + block stats] ----
__global__ __launch_bounds__(256) void fused_a_k(const float* __restrict__ g2,
                                                 float* __restrict__ outp, int n, int WB) {
    __shared__ float red[256];
    __shared__ unsigned long long redk[256];
    int t = threadIdx.x;
    if ((int)blockIdx.x < WB) {
        float M = d_scr.zmax[0];
        float invS = 1.0f / d_scr.S[0];
        int j4 = blockIdx.x * 256 + t;
        int j = j4 * 4;
        if (j < n) {
            float4 z = *(const float4*)(d_z1 + j);
            float4 o;
            o.x = expf(z.x - M) * invS;
            o.y = expf(z.y - M) * invS;
            o.z = expf(z.z - M) * invS;
            o.w = expf(z.w - M) * invS;
            *(float4*)(outp + j) = o;
        }
        return;
    }
    int b = blockIdx.x - WB;
    int j4 = b * 256 + t;
    int j = j4 * 4;
    bool valid = (j < n);
    float4 z = make_float4(0.f, 0.f, 0.f, 0.f);
    if (valid) {
        float4 l = *(const float4*)(d_l2 + j);
        uchar4 cn = *(const uchar4*)(d_conn + j);
        float4 g = *(const float4*)(g2 + j);
        z.x = ((cn.x ? MASKV : l.x) + g.x) * INV_TAU;
        z.y = ((cn.y ? MASKV : l.y) + g.y) * INV_TAU;
        z.z = ((cn.z ? MASKV : l.z) + g.z) * INV_TAU;
        z.w = ((cn.w ? MASKV : l.w) + g.w) * INV_TAU;
        *(float4*)(d_z2 + j) = z;
    }
    float lm = valid ? fmaxf(fmaxf(z.x, z.y), fmaxf(z.z, z.w)) : -1e30f;
    red[t] = lm;
    __syncthreads();
    for (int s = 128; s > 0; s >>= 1) {
        if (t < s) red[t] = fmaxf(red[t], red[t + s]);
        __syncthreads();
    }
    float bm = red[0];
    __syncthreads();
    float ls = 0.f;
    if (valid) ls = expf(z.x - bm) + expf(z.y - bm) + expf(z.z - bm) + expf(z.w - bm);
    red[t] = ls;
    unsigned long long key = 0ull;
    if (valid) {
        key = mkkey(z.x, j);
        unsigned long long k1 = mkkey(z.y, j + 1); if (k1 > key) key = k1;
        unsigned long long k2 = mkkey(z.z, j + 2); if (k2 > key) key = k2;
        unsigned long long k3 = mkkey(z.w, j + 3); if (k3 > key) key = k3;
    }
    redk[t] = key;
    __syncthreads();
    for (int s = 128; s > 0; s >>= 1) {
        if (t < s) {
            red[t] += red[t + s];
            if (redk[t + s] > redk[t]) redk[t] = redk[t + s];
        }
        __syncthreads();
    }
    if (t == 0) {
        d_bm[1][b] = bm;
        d_bs[1][b] = red[0];
        d_bk[1][b] = redk[0];
    }
}

// ---------------- fused B: [esoft] || [write n2_soft] ----------------
__global__ __launch_bounds__(256) void fused_b_k(const __half* __restrict__ G,
                                                 const float* __restrict__ eW,
                                                 const float* __restrict__ eb,
                                                 const float* __restrict__ ge,
                                                 float* __restrict__ outp, int n) {
    int t = threadIdx.x;
    if (blockIdx.x == 0) {
        __shared__ float red3[3][128];
        int i1 = d_scr.isel[0];
        int i2 = d_scr.isel[1];
        if (t < 128) {
            float a = __half2float(G[(size_t)i1 * 128 + t]);
            float b = __half2float(G[(size_t)i2 * 128 + t]);
#pragma unroll
            for (int o = 0; o < 3; o++)
                red3[o][t] = a * eW[t * 3 + o] + b * eW[(128 + t) * 3 + o];
        }
        __syncthreads();
        for (int s = 64; s > 0; s >>= 1) {
            if (t < s) {
                red3[0][t] += red3[0][t + s];
                red3[1][t] += red3[1][t + s];
                red3[2][t] += red3[2][t + s];
            }
            __syncthreads();
        }
        if (t == 0) {
            float z0 = (red3[0][0] + eb[0] + ge[0]) * INV_TAU;
            float z1v = (red3[1][0] + eb[1] + ge[1]) * INV_TAU;
            float z2v = (red3[2][0] + eb[2] + ge[2]) * INV_TAU;
            float m = fmaxf(z0, fmaxf(z1v, z2v));
            float e0 = expf(z0 - m), e1 = expf(z1v - m), e2 = expf(z2v - m);
            float inv = 1.0f / (e0 + e1 + e2);
            outp[2 * n + 0] = e0 * inv;
            outp[2 * n + 1] = e1 * inv;
            outp[2 * n + 2] = e2 * inv;
            outp[2 * n + 3] = 1.0f;
        }
        return;
    }
    float M = d_scr.zmax[1];
    float invS = 1.0f / d_scr.S[1];
    int j4 = (blockIdx.x - 1) * 256 + t;
    int j = j4 * 4;
    if (j < n) {
        float4 z = *(const float4*)(d_z2 + j);
        float4 o;
        o.x = expf(z.x - M) * invS;
        o.y = expf(z.y - M) * invS;
        o.z = expf(z.z - M) * invS;
        o.w = expf(z.w - M) * invS;
        *(float4*)(outp + n + j) = o;
    }
}

// ---------------- launcher (single stream — graph-capture safe) ----------
extern "C" void kernel_launch(void* const* d_in, const int* in_sizes, int n_in,
                              void* d_out, int out_size) {
    const float* x   = (const float*)d_in[0];
    const int*   ei  = (const int*)  d_in[1];
    const float* W1  = (const float*)d_in[2];
    const float* b1  = (const float*)d_in[3];
    const float* W2  = (const float*)d_in[4];
    const float* b2  = (const float*)d_in[5];
    const float* W3  = (const float*)d_in[6];
    const float* b3  = (const float*)d_in[7];
    const float* n1W = (const float*)d_in[8];
    const float* n1b = (const float*)d_in[9];
    const float* n2W = (const float*)d_in[10];
    const float* n2b = (const float*)d_in[11];
    const float* eW  = (const float*)d_in[12];
    const float* eb  = (const float*)d_in[13];
    const float* g1  = (const float*)d_in[16];
    const float* g2  = (const float*)d_in[17];
    const float* ge  = (const float*)d_in[18];
    float* out = (float*)d_out;

    int n = in_sizes[0] / 128;
    int E = in_sizes[1] / 2;
    const int* srcp = ei;
    const int* dstp = ei + E;

    void *pc, *pconn, *pscr, *pH, *pP, *pQ;
    cudaGetSymbolAddress(&pc,    d_counts);
    cudaGetSymbolAddress(&pconn, d_conn);
    cudaGetSymbolAddress(&pscr,  d_scr);
    cudaGetSymbolAddress(&pH,    d_H);
    cudaGetSymbolAddress(&pP,    d_P);
    cudaGetSymbolAddress(&pQ,    d_Q);
    __half* H = (__half*)pH;
    __half* P = (__half*)pP;
    __half* Q = (__half*)pQ;

    const int GEMM_SMEM = 64 * XS_H * 2 + 64 * BS_W * 4;  // 51200 B
    cudaFuncSetAttribute(gemm_f16_k, cudaFuncAttributeMaxDynamicSharedMemorySize, GEMM_SMEM);

    cudaMemsetAsync(pc,    0, (size_t)n * sizeof(int), 0);
    cudaMemsetAsync(pconn, 0, (size_t)n, 0);
    cudaMemsetAsync(pscr,  0, sizeof(Scr), 0);

    int eblocks = (E + 255) / 256;
    int nb = (n + 1023) / 1024;
    degcount_k<<<eblocks, 256>>>(dstp, E);
    scan1_k<<<nb, 1024>>>(n);
    scan2_k<<<1, 128>>>(nb, n);
    scan3_k<<<nb, 1024>>>(n);
    fill_csr_k<<<eblocks, 256>>>(srcp, dstp, E);

    int gblocks = (n + 63) / 64;
    int ablocks = (n + 15) / 16;        // half-warp per node

    gemm_f16_k<<<gblocks, 256, GEMM_SMEM>>>(P, x, 1, W1, H, n);  // fused fp32->fp16
    aggregate_k<<<ablocks, 256>>>(H, b1, Q, n, 0);
    gemm_f16_k<<<gblocks, 256, GEMM_SMEM>>>(Q, 0, 0, W2, H, n);
    aggregate_k<<<ablocks, 256>>>(H, b2, P, n, 0);
    gemm_f16_k<<<gblocks, 256, GEMM_SMEM>>>(P, 0, 0, W3, H, n);
    aggregate_k<<<ablocks, 256>>>(H, b3, Q, n, 1);  // Q = gcn, pool fused

    int halfblocks = (n / 4 + 255) / 256;       // 98
    gemv_heads_k<<<2 * halfblocks, 256>>>(n1W, n1b, g1, n2W, n2b, n, halfblocks,
                                          1.0f / (float)n);
    merge_k<<<1, 128>>>(0, halfblocks);
    conn_k<<<eblocks, 256>>>(srcp, dstp, E);

    int WB = (n + 1023) / 1024;                  // 98
    fused_a_k<<<2 * WB, 256>>>(g2, out, n, WB);
    merge_k<<<1, 128>>>(1, WB);
    fused_b_k<<<WB + 1, 256>>>(Q, eW, eb, ge, out, n);
}

// round 12
// speedup vs baseline: 1.3742x; 1.3742x over previous
#include <cuda_runtime.h>
#include <cuda_bf16.h>
#include <cuda_fp16.h>

#define NMAX 100000
#define EMAX 1600000
#define MASKV (-1000000000.0f)
#define INV_TAU 2.0f

// ---------------- device scratch (static allocation only) ----------------
struct Scr {
    float poolsum[128];
    unsigned int poolmax[128];
    float zmax[2];
    float S[2];
    int isel[2];
};

__device__ __half d_H[NMAX * 128];   // GEMM output (pre-aggregation)
__device__ __half d_P[NMAX * 128];   // activation ping
__device__ __half d_Q[NMAX * 128];   // activation pong
__device__ int    d_counts[NMAX];
__device__ int    d_rowstart[NMAX + 1];
__device__ int    d_cursor[NMAX];
__device__ int    d_csr[EMAX];
__device__ float  d_dinv[NMAX];
__device__ float  d_z1[NMAX];
__device__ float  d_l2[NMAX];
__device__ float  d_z2[NMAX];
__device__ unsigned char d_conn[NMAX];
__device__ int    d_bsum[128];
__device__ int    d_boff[128];
__device__ float  d_bm[2][128];
__device__ float  d_bs[2][128];
__device__ unsigned long long d_bk[2][128];
__device__ Scr    d_scr;

// ---------------- CSR build ----------------
__global__ void degcount_k(const int* __restrict__ dstp, int E) {
    int e = blockIdx.x * blockDim.x + threadIdx.x;
    if (e < E) atomicAdd(&d_counts[dstp[e]], 1);
}

__global__ void scan1_k(int n) {
    __shared__ int sm[1024];
    int t = threadIdx.x;
    int i = blockIdx.x * 1024 + t;
    int v = (i < n) ? d_counts[i] : 0;
    sm[t] = v;
    __syncthreads();
    for (int s = 512; s > 0; s >>= 1) {
        if (t < s) sm[t] += sm[t + s];
        __syncthreads();
    }
    if (t == 0) d_bsum[blockIdx.x] = sm[0];
}

__global__ void scan2_k(int nb, int n) {
    __shared__ int sm[128];
    int t = threadIdx.x;
    int v = (t < nb) ? d_bsum[t] : 0;
    sm[t] = v;
    __syncthreads();
    for (int d = 1; d < 128; d <<= 1) {
        int add = (t >= d) ? sm[t - d] : 0;
        __syncthreads();
        sm[t] += add;
        __syncthreads();
    }
    if (t < nb) d_boff[t] = sm[t] - v;
    if (t == nb - 1) d_rowstart[n] = sm[t];
}

__global__ void scan3_k(int n) {
    __shared__ int sm[1024];
    int t = threadIdx.x;
    int i = blockIdx.x * 1024 + t;
    int v = (i < n) ? d_counts[i] : 0;
    sm[t] = v;
    __syncthreads();
    for (int d = 1; d < 1024; d <<= 1) {
        int add = (t >= d) ? sm[t - d] : 0;
        __syncthreads();
        sm[t] += add;
        __syncthreads();
    }
    if (i < n) {
        int excl = sm[t] - v + d_boff[blockIdx.x];
        d_rowstart[i] = excl;
        d_cursor[i]   = excl;
        d_dinv[i]     = rsqrtf((float)v + 1.0f);
    }
}

__global__ void fill_csr_k(const int* __restrict__ srcp, const int* __restrict__ dstp, int E) {
    int e = blockIdx.x * blockDim.x + threadIdx.x;
    if (e < E) {
        int d = dstp[e];
        int pos = atomicAdd(&d_cursor[d], 1);
        d_csr[pos] = srcp[e];
    }
}

// ---------------- fp16 tensor-core GEMM: Hout = fp16(dinv * (X @ W)) ------
// xf32 != 0: X32 is the fp32 input (layer 1, converts during smem store).
#define XS_H 136
#define BS_W 132

__device__ __forceinline__ void mma_f16(float* d,
                                        unsigned a0, unsigned a1, unsigned a2, unsigned a3,
                                        unsigned b0, unsigned b1) {
    asm volatile("mma.sync.aligned.m16n8k16.row.col.f32.f16.f16.f32 "
                 "{%0,%1,%2,%3}, {%4,%5,%6,%7}, {%8,%9}, {%0,%1,%2,%3};"
                 : "+f"(d[0]), "+f"(d[1]), "+f"(d[2]), "+f"(d[3])
                 : "r"(a0), "r"(a1), "r"(a2), "r"(a3), "r"(b0), "r"(b1));
}

__global__ __launch_bounds__(256) void gemm_f16_k(const __half* __restrict__ X,
                                                  const float* __restrict__ X32,
                                                  int xf32,
                                                  const float* __restrict__ W,
                                                  __half* __restrict__ Hout, int n) {
    extern __shared__ char shraw[];
    __half*  xs = (__half*)shraw;                    // 64 x XS_H halfs
    __half2* bs = (__half2*)(shraw + 64 * XS_H * 2); // 64 x BS_W half2 (k-pairs)

    int t = threadIdx.x;
    int row0 = blockIdx.x * 64;
    int nr = n - row0; if (nr > 64) nr = 64;

    for (int i = t; i < 64 * 128; i += 256) {
        int k2 = i >> 7, nn = i & 127;
        float w0 = W[(size_t)(2 * k2) * 128 + nn];
        float w1 = W[(size_t)(2 * k2 + 1) * 128 + nn];
        bs[k2 * BS_W + nn] = __floats2half2_rn(w0, w1);
    }
    if (xf32) {
        // fp32 rows -> fp16 smem (identical rounding to a separate cvt pass)
        for (int i = t; i < nr * 32; i += 256) {
            int rr = i >> 5, c4 = i & 31;
            float4 v = *(const float4*)(X32 + (size_t)(row0 + rr) * 128 + c4 * 4);
            __half2 a = __floats2half2_rn(v.x, v.y);
            __half2 b = __floats2half2_rn(v.z, v.w);
            *(uint2*)(xs + rr * XS_H + c4 * 4) = make_uint2(*(unsigned*)&a, *(unsigned*)&b);
        }
    } else {
        for (int i = t; i < nr * 16; i += 256) {
            int rr = i >> 4, c8 = i & 15;
            uint4 v = *(const uint4*)(X + (size_t)(row0 + rr) * 128 + c8 * 8);
            *(uint4*)(xs + rr * XS_H + c8 * 8) = v;
        }
    }
    __syncthreads();

    int lane = t & 31, wid = t >> 5;
    int wm = wid & 1, wn = wid >> 1;
    int m0 = wm * 32, n0 = wn * 32;
    int r = lane >> 2, c = lane & 3;

    float acc[2][4][4];
#pragma unroll
    for (int mi = 0; mi < 2; mi++)
#pragma unroll
        for (int nj = 0; nj < 4; nj++)
#pragma unroll
            for (int q = 0; q < 4; q++) acc[mi][nj][q] = 0.f;

#pragma unroll
    for (int k0 = 0; k0 < 8; k0++) {
        unsigned a[2][4];
#pragma unroll
        for (int mi = 0; mi < 2; mi++) {
            const __half* xb = xs + (m0 + mi * 16 + r) * XS_H + k0 * 16 + 2 * c;
            a[mi][0] = *(const unsigned*)(xb);
            a[mi][1] = *(const unsigned*)(xb + 8 * XS_H);
            a[mi][2] = *(const unsigned*)(xb + 8);
            a[mi][3] = *(const unsigned*)(xb + 8 * XS_H + 8);
        }
#pragma unroll
        for (int nj = 0; nj < 4; nj++) {
            const __half2* bb = bs + (k0 * 8 + c) * BS_W + n0 + nj * 8 + r;
            unsigned b0 = *(const unsigned*)(bb);
            unsigned b1 = *(const unsigned*)(bb + 4 * BS_W);
#pragma unroll
            for (int mi = 0; mi < 2; mi++)
                mma_f16(acc[mi][nj], a[mi][0], a[mi][1], a[mi][2], a[mi][3], b0, b1);
        }
    }

#pragma unroll
    for (int mi = 0; mi < 2; mi++) {
        int rloc = m0 + mi * 16 + r;
        float s0 = 0.f, s1 = 0.f;
        if (rloc < nr)     s0 = d_dinv[row0 + rloc];
        if (rloc + 8 < nr) s1 = d_dinv[row0 + rloc + 8];
#pragma unroll
        for (int nj = 0; nj < 4; nj++) {
            int col = n0 + nj * 8 + 2 * c;
            if (rloc < nr) {
                __half2 h = __floats2half2_rn(acc[mi][nj][0] * s0, acc[mi][nj][1] * s0);
                *(__half2*)(Hout + (size_t)(row0 + rloc) * 128 + col) = h;
            }
            if (rloc + 8 < nr) {
                __half2 h = __floats2half2_rn(acc[mi][nj][2] * s1, acc[mi][nj][3] * s1);
                *(__half2*)(Hout + (size_t)(row0 + rloc + 8) * 128 + col) = h;
            }
        }
    }
}

// ---------------- aggregation: half-warp per node, 4-deep pipeline --------
// (exact Round-10 structure; segment-masked shuffles)
__global__ __launch_bounds__(256) void aggregate_k(const __half* __restrict__ H,
                                                   const float* __restrict__ bias,
                                                   __half* __restrict__ outp, int n,
                                                   int dopool) {
    __shared__ float pS[16][128];
    __shared__ float pM[16][128];
    int t = threadIdx.x;
    int hw = t >> 4;          // half-warp id in block, 0..15
    int lane16 = t & 15;
    int w = blockIdx.x * 16 + hw;
    unsigned hmask = 0xFFFFu << (t & 16);   // this half-warp's lanes only

    float o[8];
#pragma unroll
    for (int q = 0; q < 8; q++) o[q] = 0.f;

    if (w < n) {
        float acc[8];
#pragma unroll
        for (int q = 0; q < 8; q++) acc[q] = 0.f;
        int beg = d_rowstart[w];
        int end = d_rowstart[w + 1];
        const __half* Hl = H + lane16 * 8;
        for (int base = beg; base < end; base += 16) {
            int rem = end - base;
            int cnt = rem < 16 ? rem : 16;
            int idx = (lane16 < cnt) ? d_csr[base + lane16] : 0;
            uint4 h[4];
            int m0 = cnt < 4 ? cnt : 4;
#pragma unroll
            for (int u = 0; u < 4; u++) {
                if (u < m0) {
                    int s = __shfl_sync(hmask, idx, u, 16);
                    h[u] = *(const uint4*)(Hl + (size_t)s * 128);
                }
            }
            for (int j0 = 0; j0 < cnt; j0 += 4) {
                int curm = cnt - j0; if (curm > 4) curm = 4;
                int nxtm = cnt - j0 - 4;
                if (nxtm < 0) nxtm = 0;
                if (nxtm > 4) nxtm = 4;
                uint4 h2[4];
#pragma unroll
                for (int u = 0; u < 4; u++) {
                    if (u < nxtm) {
                        int s = __shfl_sync(hmask, idx, j0 + 4 + u, 16);
                        h2[u] = *(const uint4*)(Hl + (size_t)s * 128);
                    } else {
                        h2[u] = make_uint4(0u, 0u, 0u, 0u);
                    }
                }
#pragma unroll
                for (int u = 0; u < 4; u++) {
                    if (u < curm) {
                        const __half2* p2 = (const __half2*)&h[u];
#pragma unroll
                        for (int q = 0; q < 4; q++) {
                            float2 f = __half22float2(p2[q]);
                            acc[2 * q]     += f.x;
                            acc[2 * q + 1] += f.y;
                        }
                    }
                }
#pragma unroll
                for (int u = 0; u < 4; u++) h[u] = h2[u];
            }
        }
        // self-loop
        {
            uint4 hs = *(const uint4*)(Hl + (size_t)w * 128);
            const __half2* p2 = (const __half2*)&hs;
#pragma unroll
            for (int q = 0; q < 4; q++) {
                float2 f = __half22float2(p2[q]);
                acc[2 * q]     += f.x;
                acc[2 * q + 1] += f.y;
            }
        }
        float di = d_dinv[w];
        float4 b0 = *(const float4*)(bias + lane16 * 8);
        float4 b1 = *(const float4*)(bias + lane16 * 8 + 4);
        o[0] = fmaxf(di * acc[0] + b0.x, 0.f);
        o[1] = fmaxf(di * acc[1] + b0.y, 0.f);
        o[2] = fmaxf(di * acc[2] + b0.z, 0.f);
        o[3] = fmaxf(di * acc[3] + b0.w, 0.f);
        o[4] = fmaxf(di * acc[4] + b1.x, 0.f);
        o[5] = fmaxf(di * acc[5] + b1.y, 0.f);
        o[6] = fmaxf(di * acc[6] + b1.z, 0.f);
        o[7] = fmaxf(di * acc[7] + b1.w, 0.f);
        __half2 ho[4];
#pragma unroll
        for (int q = 0; q < 4; q++) ho[q] = __floats2half2_rn(o[2 * q], o[2 * q + 1]);
        *(uint4*)(outp + (size_t)w * 128 + lane16 * 8) = *(uint4*)ho;
    }

    if (dopool) {
#pragma unroll
        for (int q = 0; q < 8; q++) {
            pS[hw][lane16 * 8 + q] = o[q];
            pM[hw][lane16 * 8 + q] = o[q];
        }
        __syncthreads();
        if (t < 128) {
            float s = 0.f, mx = 0.f;
#pragma unroll
            for (int u = 0; u < 16; u++) { s += pS[u][t]; mx = fmaxf(mx, pM[u][t]); }
            atomicAdd(&d_scr.poolsum[t], s);
            atomicMax(&d_scr.poolmax[t], __float_as_uint(mx));
        }
    }
}

// ---------------- argmax key helpers ----------------
__device__ __forceinline__ unsigned enc_f(float f) {
    unsigned u = __float_as_uint(f);
    return (u & 0x80000000u) ? ~u : (u | 0x80000000u);
}
__device__ __forceinline__ unsigned long long mkkey(float f, int j) {
    return ((unsigned long long)enc_f(f) << 32) | (unsigned long long)(0xFFFFFFFFu - (unsigned)j);
}

// ---------------- head GEMVs + inline pool final + z1 block stats ----------
__global__ __launch_bounds__(256) void gemv_heads_k(const float* __restrict__ n1W,
                                                    const float* __restrict__ n1b,
                                                    const float* __restrict__ g1,
                                                    const float* __restrict__ n2W,
                                                    const float* __restrict__ n2b,
                                                    int ncols, int halfblocks, float inv_n) {
    __shared__ float p[256];
    __shared__ float red[256];
    __shared__ unsigned long long redk[256];
    int t = threadIdx.x;
    if (t < 128) p[t] = d_scr.poolsum[t] * inv_n;
    else         p[t] = __uint_as_float(d_scr.poolmax[t - 128]);
    __syncthreads();
    int second = blockIdx.x >= halfblocks;
    int b = second ? blockIdx.x - halfblocks : blockIdx.x;
    int j4 = b * blockDim.x + t;
    bool valid = (j4 * 4 < ncols);
    float ax = 0.f, ay = 0.f, az = 0.f, aw = 0.f;
    if (valid) {
        const float* W = second ? n2W : n1W;
#pragma unroll 4
        for (int k = 0; k < 256; k++) {
            float4 w4 = *(const float4*)(W + (size_t)k * ncols + j4 * 4);
            float pv = p[k];
            ax += pv * w4.x; ay += pv * w4.y; az += pv * w4.z; aw += pv * w4.w;
        }
    }
    int j = j4 * 4;
    if (!second) {
        float4 o = make_float4(0.f, 0.f, 0.f, 0.f);
        if (valid) {
            float4 bb = *(const float4*)(n1b + j);
            float4 gg = *(const float4*)(g1 + j);
            o.x = (ax + bb.x + gg.x) * INV_TAU;
            o.y = (ay + bb.y + gg.y) * INV_TAU;
            o.z = (az + bb.z + gg.z) * INV_TAU;
            o.w = (aw + bb.w + gg.w) * INV_TAU;
            *(float4*)(d_z1 + j) = o;
        }
        float lm = valid ? fmaxf(fmaxf(o.x, o.y), fmaxf(o.z, o.w)) : -1e30f;
        red[t] = lm;
        __syncthreads();
        for (int s = 128; s > 0; s >>= 1) {
            if (t < s) red[t] = fmaxf(red[t], red[t + s]);
            __syncthreads();
        }
        float bm = red[0];
        __syncthreads();
        float ls = 0.f;
        if (valid) {
            ls = expf(o.x - bm) + expf(o.y - bm) + expf(o.z - bm) + expf(o.w - bm);
        }
        red[t] = ls;
        unsigned long long key = 0ull;
        if (valid) {
            key = mkkey(o.x, j);
            unsigned long long k1 = mkkey(o.y, j + 1); if (k1 > key) key = k1;
            unsigned long long k2 = mkkey(o.z, j + 2); if (k2 > key) key = k2;
            unsigned long long k3 = mkkey(o.w, j + 3); if (k3 > key) key = k3;
        }
        redk[t] = key;
        __syncthreads();
        for (int s = 128; s > 0; s >>= 1) {
            if (t < s) {
                red[t] += red[t + s];
                if (redk[t + s] > redk[t]) redk[t] = redk[t + s];
            }
            __syncthreads();
        }
        if (t == 0) {
            d_bm[0][b] = bm;
            d_bs[0][b] = red[0];
            d_bk[0][b] = redk[0];
        }
    } else {
        if (valid) {
            float4 bb = *(const float4*)(n2b + j);
            float4 o;
            o.x = ax + bb.x; o.y = ay + bb.y; o.z = az + bb.z; o.w = aw + bb.w;
            *(float4*)(d_l2 + j) = o;
        }
    }
}

// ---------------- merge block stats -> global M, S, argmax ----------------
__global__ void merge_k(int which, int nb) {
    __shared__ float sm[128];
    __shared__ float ss[128];
    __shared__ unsigned long long sk[128];
    int t = threadIdx.x;  // 128
    float m = (t < nb) ? d_bm[which][t] : -1e30f;
    sm[t] = m;
    __syncthreads();
    for (int s = 64; s > 0; s >>= 1) {
        if (t < s) sm[t] = fmaxf(sm[t], sm[t + s]);
        __syncthreads();
    }
    float M = sm[0];
    __syncthreads();
    float ls = (t < nb) ? d_bs[which][t] * expf(d_bm[which][t] - M) : 0.f;
    ss[t] = ls;
    sk[t] = (t < nb) ? d_bk[which][t] : 0ull;
    __syncthreads();
    for (int s = 64; s > 0; s >>= 1) {
        if (t < s) {
            ss[t] += ss[t + s];
            if (sk[t + s] > sk[t]) sk[t] = sk[t + s];
        }
        __syncthreads();
    }
    if (t == 0) {
        d_scr.zmax[which] = M;
        d_scr.S[which] = ss[0];
        int idx = (int)(0xFFFFFFFFu - (unsigned)(sk[0] & 0xFFFFFFFFull));
        d_scr.isel[which] = idx;
        if (which == 0) d_conn[idx] = 1;
    }
}

// ---------------- mask of nodes connected to i1 ----------------
__global__ void conn_k(const int* __restrict__ srcp, const int* __restrict__ dstp, int E) {
    int i1 = d_scr.isel[0];
    int e = blockIdx.x * blockDim.x + threadIdx.x;
    if (e < E) {
        int s = srcp[e], d = dstp[e];
        if (s == i1 || d == i1) { d_conn[s] = 1; d_conn[d] = 1; }
    }
}

// ---------------- fused A: [write n1_soft] || [z2 compute + block stats] ----
__global__ __launch_bounds__(256) void fused_a_k(const float* __restrict__ g2,
                                                 float* __restrict__ outp, int n, int WB) {
    __shared__ float red[256];
    __shared__ unsigned long long redk[256];
    int t = threadIdx.x;
    if ((int)blockIdx.x < WB) {
        float M = d_scr.zmax[0];
        float invS = 1.0f / d_scr.S[0];
        int j4 = blockIdx.x * 256 + t;
        int j = j4 * 4;
        if (j < n) {
            float4 z = *(const float4*)(d_z1 + j);
            float4 o;
            o.x = expf(z.x - M) * invS;
            o.y = expf(z.y - M) * invS;
            o.z = expf(z.z - M) * invS;
            o.w = expf(z.w - M) * invS;
            *(float4*)(outp + j) = o;
        }
        return;
    }
    int b = blockIdx.x - WB;
    int j4 = b * 256 + t;
    int j = j4 * 4;
    bool valid = (j < n);
    float4 z = make_float4(0.f, 0.f, 0.f, 0.f);
    if (valid) {
        float4 l = *(const float4*)(d_l2 + j);
        uchar4 cn = *(const uchar4*)(d_conn + j);
        float4 g = *(const float4*)(g2 + j);
        z.x = ((cn.x ? MASKV : l.x) + g.x) * INV_TAU;
        z.y = ((cn.y ? MASKV : l.y) + g.y) * INV_TAU;
        z.z = ((cn.z ? MASKV : l.z) + g.z) * INV_TAU;
        z.w = ((cn.w ? MASKV : l.w) + g.w) * INV_TAU;
        *(float4*)(d_z2 + j) = z;
    }
    float lm = valid ? fmaxf(fmaxf(z.x, z.y), fmaxf(z.z, z.w)) : -1e30f;
    red[t] = lm;
    __syncthreads();
    for (int s = 128; s > 0; s >>= 1) {
        if (t < s) red[t] = fmaxf(red[t], red[t + s]);
        __syncthreads();
    }
    float bm = red[0];
    __syncthreads();
    float ls = 0.f;
    if (valid) ls = expf(z.x - bm) + expf(z.y - bm) + expf(z.z - bm) + expf(z.w - bm);
    red[t] = ls;
    unsigned long long key = 0ull;
    if (valid) {
        key = mkkey(z.x, j);
        unsigned long long k1 = mkkey(z.y, j + 1); if (k1 > key) key = k1;
        unsigned long long k2 = mkkey(z.z, j + 2); if (k2 > key) key = k2;
        unsigned long long k3 = mkkey(z.w, j + 3); if (k3 > key) key = k3;
    }
    redk[t] = key;
    __syncthreads();
    for (int s = 128; s > 0; s >>= 1) {
        if (t < s) {
            red[t] += red[t + s];
            if (redk[t + s] > redk[t]) redk[t] = redk[t + s];
        }
        __syncthreads();
    }
    if (t == 0) {
        d_bm[1][b] = bm;
        d_bs[1][b] = red[0];
        d_bk[1][b] = redk[0];
    }
}

// ---------------- fused B: [esoft] || [write n2_soft] ----------------
__global__ __launch_bounds__(256) void fused_b_k(const __half* __restrict__ G,
                                                 const float* __restrict__ eW,
                                                 const float* __restrict__ eb,
                                                 const float* __restrict__ ge,
                                                 float* __restrict__ outp, int n) {
    int t = threadIdx.x;
    if (blockIdx.x == 0) {
        __shared__ float red3[3][128];
        int i1 = d_scr.isel[0];
        int i2 = d_scr.isel[1];
        if (t < 128) {
            float a = __half2float(G[(size_t)i1 * 128 + t]);
            float b = __half2float(G[(size_t)i2 * 128 + t]);
#pragma unroll
            for (int o = 0; o < 3; o++)
                red3[o][t] = a * eW[t * 3 + o] + b * eW[(128 + t) * 3 + o];
        }
        __syncthreads();
        for (int s = 64; s > 0; s >>= 1) {
            if (t < s) {
                red3[0][t] += red3[0][t + s];
                red3[1][t] += red3[1][t + s];
                red3[2][t] += red3[2][t + s];
            }
            __syncthreads();
        }
        if (t == 0) {
            float z0 = (red3[0][0] + eb[0] + ge[0]) * INV_TAU;
            float z1v = (red3[1][0] + eb[1] + ge[1]) * INV_TAU;
            float z2v = (red3[2][0] + eb[2] + ge[2]) * INV_TAU;
            float m = fmaxf(z0, fmaxf(z1v, z2v));
            float e0 = expf(z0 - m), e1 = expf(z1v - m), e2 = expf(z2v - m);
            float inv = 1.0f / (e0 + e1 + e2);
            outp[2 * n + 0] = e0 * inv;
            outp[2 * n + 1] = e1 * inv;
            outp[2 * n + 2] = e2 * inv;
            outp[2 * n + 3] = 1.0f;
        }
        return;
    }
    float M = d_scr.zmax[1];
    float invS = 1.0f / d_scr.S[1];
    int j4 = (blockIdx.x - 1) * 256 + t;
    int j = j4 * 4;
    if (j < n) {
        float4 z = *(const float4*)(d_z2 + j);
        float4 o;
        o.x = expf(z.x - M) * invS;
        o.y = expf(z.y - M) * invS;
        o.z = expf(z.z - M) * invS;
        o.w = expf(z.w - M) * invS;
        *(float4*)(outp + n + j) = o;
    }
}

// ---------------- launcher (single stream — graph-capture safe) ----------
extern "C" void kernel_launch(void* const* d_in, const int* in_sizes, int n_in,
                              void* d_out, int out_size) {
    const float* x   = (const float*)d_in[0];
    const int*   ei  = (const int*)  d_in[1];
    const float* W1  = (const float*)d_in[2];
    const float* b1  = (const float*)d_in[3];
    const float* W2  = (const float*)d_in[4];
    const float* b2  = (const float*)d_in[5];
    const float* W3  = (const float*)d_in[6];
    const float* b3  = (const float*)d_in[7];
    const float* n1W = (const float*)d_in[8];
    const float* n1b = (const float*)d_in[9];
    const float* n2W = (const float*)d_in[10];
    const float* n2b = (const float*)d_in[11];
    const float* eW  = (const float*)d_in[12];
    const float* eb  = (const float*)d_in[13];
    const float* g1  = (const float*)d_in[16];
    const float* g2  = (const float*)d_in[17];
    const float* ge  = (const float*)d_in[18];
    float* out = (float*)d_out;

    int n = in_sizes[0] / 128;
    int E = in_sizes[1] / 2;
    const int* srcp = ei;
    const int* dstp = ei + E;

    void *pc, *pconn, *pscr, *pH, *pP, *pQ;
    cudaGetSymbolAddress(&pc,    d_counts);
    cudaGetSymbolAddress(&pconn, d_conn);
    cudaGetSymbolAddress(&pscr,  d_scr);
    cudaGetSymbolAddress(&pH,    d_H);
    cudaGetSymbolAddress(&pP,    d_P);
    cudaGetSymbolAddress(&pQ,    d_Q);
    __half* H = (__half*)pH;
    __half* P = (__half*)pP;
    __half* Q = (__half*)pQ;

    const int GEMM_SMEM = 64 * XS_H * 2 + 64 * BS_W * 4;  // 51200 B
    cudaFuncSetAttribute(gemm_f16_k, cudaFuncAttributeMaxDynamicSharedMemorySize, GEMM_SMEM);

    cudaMemsetAsync(pc,    0, (size_t)n * sizeof(int), 0);
    cudaMemsetAsync(pconn, 0, (size_t)n, 0);
    cudaMemsetAsync(pscr,  0, sizeof(Scr), 0);

    int eblocks = (E + 255) / 256;
    int nb = (n + 1023) / 1024;
    degcount_k<<<eblocks, 256>>>(dstp, E);
    scan1_k<<<nb, 1024>>>(n);
    scan2_k<<<1, 128>>>(nb, n);
    scan3_k<<<nb, 1024>>>(n);
    fill_csr_k<<<eblocks, 256>>>(srcp, dstp, E);

    int gblocks = (n + 63) / 64;
    int ablocks = (n + 15) / 16;        // half-warp per node

    gemm_f16_k<<<gblocks, 256, GEMM_SMEM>>>(P, x, 1, W1, H, n);  // fused fp32->fp16
    aggregate_k<<<ablocks, 256>>>(H, b1, Q, n, 0);
    gemm_f16_k<<<gblocks, 256, GEMM_SMEM>>>(Q, 0, 0, W2, H, n);
    aggregate_k<<<ablocks, 256>>>(H, b2, P, n, 0);
    gemm_f16_k<<<gblocks, 256, GEMM_SMEM>>>(P, 0, 0, W3, H, n);
    aggregate_k<<<ablocks, 256>>>(H, b3, Q, n, 1);  // Q = gcn, pool fused

    int halfblocks = (n / 4 + 255) / 256;       // 98
    gemv_heads_k<<<2 * halfblocks, 256>>>(n1W, n1b, g1, n2W, n2b, n, halfblocks,
                                          1.0f / (float)n);
    merge_k<<<1, 128>>>(0, halfblocks);
    conn_k<<<eblocks, 256>>>(srcp, dstp, E);

    int WB = (n + 1023) / 1024;                  // 98
    fused_a_k<<<2 * WB, 256>>>(g2, out, n, WB);
    merge_k<<<1, 128>>>(1, WB);
    fused_b_k<<<WB + 1, 256>>>(Q, eW, eb, ge, out, n);
}

// round 13
// speedup vs baseline: 1.4293x; 1.0401x over previous
#include <cuda_runtime.h>
#include <cuda_bf16.h>
#include <cuda_fp16.h>

#define NMAX 100000
#define EMAX 1600000
#define MASKV (-1000000000.0f)
#define INV_TAU 2.0f

// ---------------- device scratch (static allocation only) ----------------
struct Scr {
    float poolsum[128];
    unsigned int poolmax[128];
    float zmax[2];
    float S[2];
    int isel[2];
};

__device__ __half d_H[NMAX * 128];   // GEMM output (pre-aggregation)
__device__ __half d_P[NMAX * 128];   // activation ping
__device__ __half d_Q[NMAX * 128];   // activation pong
__device__ int    d_counts[NMAX];
__device__ int    d_rowstart[NMAX + 1];
__device__ int    d_cursor[NMAX];
__device__ int    d_csr[EMAX];
__device__ float  d_dinv[NMAX];
__device__ float  d_z1[NMAX];
__device__ float  d_l2[NMAX];
__device__ float  d_z2[NMAX];
__device__ unsigned char d_conn[NMAX];
__device__ int    d_bsum[128];
__device__ int    d_boff[128];
__device__ float  d_bm[2][128];
__device__ float  d_bs[2][128];
__device__ unsigned long long d_bk[2][128];
__device__ Scr    d_scr;

// ---------------- CSR build ----------------
__global__ void degcount_k(const int* __restrict__ dstp, int E) {
    int e = blockIdx.x * blockDim.x + threadIdx.x;
    if (e < E) atomicAdd(&d_counts[dstp[e]], 1);
}

__global__ void scan1_k(int n) {
    __shared__ int sm[1024];
    int t = threadIdx.x;
    int i = blockIdx.x * 1024 + t;
    int v = (i < n) ? d_counts[i] : 0;
    sm[t] = v;
    __syncthreads();
    for (int s = 512; s > 0; s >>= 1) {
        if (t < s) sm[t] += sm[t + s];
        __syncthreads();
    }
    if (t == 0) d_bsum[blockIdx.x] = sm[0];
}

__global__ void scan2_k(int nb, int n) {
    __shared__ int sm[128];
    int t = threadIdx.x;
    int v = (t < nb) ? d_bsum[t] : 0;
    sm[t] = v;
    __syncthreads();
    for (int d = 1; d < 128; d <<= 1) {
        int add = (t >= d) ? sm[t - d] : 0;
        __syncthreads();
        sm[t] += add;
        __syncthreads();
    }
    if (t < nb) d_boff[t] = sm[t] - v;
    if (t == nb - 1) d_rowstart[n] = sm[t];
}

__global__ void scan3_k(int n) {
    __shared__ int sm[1024];
    int t = threadIdx.x;
    int i = blockIdx.x * 1024 + t;
    int v = (i < n) ? d_counts[i] : 0;
    sm[t] = v;
    __syncthreads();
    for (int d = 1; d < 1024; d <<= 1) {
        int add = (t >= d) ? sm[t - d] : 0;
        __syncthreads();
        sm[t] += add;
        __syncthreads();
    }
    if (i < n) {
        int excl = sm[t] - v + d_boff[blockIdx.x];
        d_rowstart[i] = excl;
        d_cursor[i]   = excl;
        d_dinv[i]     = rsqrtf((float)v + 1.0f);
    }
}

__global__ void fill_csr_k(const int* __restrict__ srcp, const int* __restrict__ dstp, int E) {
    int e = blockIdx.x * blockDim.x + threadIdx.x;
    if (e < E) {
        int d = dstp[e];
        int pos = atomicAdd(&d_cursor[d], 1);
        d_csr[pos] = srcp[e];
    }
}

// ---------------- fp16 tensor-core GEMM: Hout = fp16(dinv * (X @ W)) ------
// xf32 != 0: X32 is the fp32 input (layer 1, converts during smem store).
#define XS_H 136
#define BS_W 132

__device__ __forceinline__ void mma_f16(float* d,
                                        unsigned a0, unsigned a1, unsigned a2, unsigned a3,
                                        unsigned b0, unsigned b1) {
    asm volatile("mma.sync.aligned.m16n8k16.row.col.f32.f16.f16.f32 "
                 "{%0,%1,%2,%3}, {%4,%5,%6,%7}, {%8,%9}, {%0,%1,%2,%3};"
                 : "+f"(d[0]), "+f"(d[1]), "+f"(d[2]), "+f"(d[3])
                 : "r"(a0), "r"(a1), "r"(a2), "r"(a3), "r"(b0), "r"(b1));
}

__global__ __launch_bounds__(256) void gemm_f16_k(const __half* __restrict__ X,
                                                  const float* __restrict__ X32,
                                                  int xf32,
                                                  const float* __restrict__ W,
                                                  __half* __restrict__ Hout, int n) {
    extern __shared__ char shraw[];
    __half*  xs = (__half*)shraw;                    // 64 x XS_H halfs
    __half2* bs = (__half2*)(shraw + 64 * XS_H * 2); // 64 x BS_W half2 (k-pairs)

    int t = threadIdx.x;
    int row0 = blockIdx.x * 64;
    int nr = n - row0; if (nr > 64) nr = 64;

    for (int i = t; i < 64 * 128; i += 256) {
        int k2 = i >> 7, nn = i & 127;
        float w0 = W[(size_t)(2 * k2) * 128 + nn];
        float w1 = W[(size_t)(2 * k2 + 1) * 128 + nn];
        bs[k2 * BS_W + nn] = __floats2half2_rn(w0, w1);
    }
    if (xf32) {
        for (int i = t; i < nr * 32; i += 256) {
            int rr = i >> 5, c4 = i & 31;
            float4 v = *(const float4*)(X32 + (size_t)(row0 + rr) * 128 + c4 * 4);
            __half2 a = __floats2half2_rn(v.x, v.y);
            __half2 b = __floats2half2_rn(v.z, v.w);
            *(uint2*)(xs + rr * XS_H + c4 * 4) = make_uint2(*(unsigned*)&a, *(unsigned*)&b);
        }
    } else {
        for (int i = t; i < nr * 16; i += 256) {
            int rr = i >> 4, c8 = i & 15;
            uint4 v = *(const uint4*)(X + (size_t)(row0 + rr) * 128 + c8 * 8);
            *(uint4*)(xs + rr * XS_H + c8 * 8) = v;
        }
    }
    __syncthreads();

    int lane = t & 31, wid = t >> 5;
    int wm = wid & 1, wn = wid >> 1;
    int m0 = wm * 32, n0 = wn * 32;
    int r = lane >> 2, c = lane & 3;

    float acc[2][4][4];
#pragma unroll
    for (int mi = 0; mi < 2; mi++)
#pragma unroll
        for (int nj = 0; nj < 4; nj++)
#pragma unroll
            for (int q = 0; q < 4; q++) acc[mi][nj][q] = 0.f;

#pragma unroll
    for (int k0 = 0; k0 < 8; k0++) {
        unsigned a[2][4];
#pragma unroll
        for (int mi = 0; mi < 2; mi++) {
            const __half* xb = xs + (m0 + mi * 16 + r) * XS_H + k0 * 16 + 2 * c;
            a[mi][0] = *(const unsigned*)(xb);
            a[mi][1] = *(const unsigned*)(xb + 8 * XS_H);
            a[mi][2] = *(const unsigned*)(xb + 8);
            a[mi][3] = *(const unsigned*)(xb + 8 * XS_H + 8);
        }
#pragma unroll
        for (int nj = 0; nj < 4; nj++) {
            const __half2* bb = bs + (k0 * 8 + c) * BS_W + n0 + nj * 8 + r;
            unsigned b0 = *(const unsigned*)(bb);
            unsigned b1 = *(const unsigned*)(bb + 4 * BS_W);
#pragma unroll
            for (int mi = 0; mi < 2; mi++)
                mma_f16(acc[mi][nj], a[mi][0], a[mi][1], a[mi][2], a[mi][3], b0, b1);
        }
    }

#pragma unroll
    for (int mi = 0; mi < 2; mi++) {
        int rloc = m0 + mi * 16 + r;
        float s0 = 0.f, s1 = 0.f;
        if (rloc < nr)     s0 = d_dinv[row0 + rloc];
        if (rloc + 8 < nr) s1 = d_dinv[row0 + rloc + 8];
#pragma unroll
        for (int nj = 0; nj < 4; nj++) {
            int col = n0 + nj * 8 + 2 * c;
            if (rloc < nr) {
                __half2 h = __floats2half2_rn(acc[mi][nj][0] * s0, acc[mi][nj][1] * s0);
                *(__half2*)(Hout + (size_t)(row0 + rloc) * 128 + col) = h;
            }
            if (rloc + 8 < nr) {
                __half2 h = __floats2half2_rn(acc[mi][nj][2] * s1, acc[mi][nj][3] * s1);
                *(__half2*)(Hout + (size_t)(row0 + rloc + 8) * 128 + col) = h;
            }
        }
    }
}

// ---------------- aggregation: half-warp per node, LOCKSTEP halves --------
// Both half-warps iterate a warp-uniform trip count (max of the two node
// degrees); invalid slots load zeros which are accumulated unconditionally
// (exact). Eliminates intra-warp divergence serialization.
__global__ __launch_bounds__(256) void aggregate_k(const __half* __restrict__ H,
                                                   const float* __restrict__ bias,
                                                   __half* __restrict__ outp, int n,
                                                   int dopool) {
    __shared__ float pS[16][128];
    __shared__ float pM[16][128];
    int t = threadIdx.x;
    int hw = t >> 4;          // half-warp id in block, 0..15
    int lane16 = t & 15;
    int w = blockIdx.x * 16 + hw;
    unsigned hmask = 0xFFFFu << (t & 16);
    bool active = (w < n);

    int beg = 0, cnt = 0;
    if (active) {
        beg = d_rowstart[w];
        cnt = d_rowstart[w + 1] - beg;
    }
    // warp-uniform trip count = max over the two halves
    int mc = cnt;
    int other = __shfl_xor_sync(0xffffffffu, cnt, 16);
    if (other > mc) mc = other;

    float acc[8];
#pragma unroll
    for (int q = 0; q < 8; q++) acc[q] = 0.f;
    const __half* Hl = H + lane16 * 8;

    for (int base = 0; base < mc; base += 16) {
        int wcnt = mc - base; if (wcnt > 16) wcnt = 16;   // warp-uniform
        int myrem = cnt - base;                           // per-half (may be <=0)
        int idx = 0;
        if (lane16 < myrem) idx = d_csr[beg + base + lane16];
        uint4 h[4];
#pragma unroll
        for (int u = 0; u < 4; u++) {
            int s = __shfl_sync(hmask, idx, u, 16);
            h[u] = (u < myrem) ? *(const uint4*)(Hl + (size_t)s * 128)
                               : make_uint4(0u, 0u, 0u, 0u);
        }
        for (int j0 = 0; j0 < wcnt; j0 += 4) {            // warp-uniform bound
            uint4 h2[4];
#pragma unroll
            for (int u = 0; u < 4; u++) {
                int jj = j0 + 4 + u;
                int s = __shfl_sync(hmask, idx, jj & 15, 16);
                h2[u] = (jj < myrem && jj < 16) ? *(const uint4*)(Hl + (size_t)s * 128)
                                                : make_uint4(0u, 0u, 0u, 0u);
            }
#pragma unroll
            for (int u = 0; u < 4; u++) {
                const __half2* p2 = (const __half2*)&h[u];
#pragma unroll
                for (int q = 0; q < 4; q++) {
                    float2 f = __half22float2(p2[q]);
                    acc[2 * q]     += f.x;
                    acc[2 * q + 1] += f.y;
                }
            }
#pragma unroll
            for (int u = 0; u < 4; u++) h[u] = h2[u];
        }
    }

    float o[8];
#pragma unroll
    for (int q = 0; q < 8; q++) o[q] = 0.f;

    if (active) {
        // self-loop
        uint4 hs = *(const uint4*)(Hl + (size_t)w * 128);
        const __half2* p2 = (const __half2*)&hs;
#pragma unroll
        for (int q = 0; q < 4; q++) {
            float2 f = __half22float2(p2[q]);
            acc[2 * q]     += f.x;
            acc[2 * q + 1] += f.y;
        }
        float di = d_dinv[w];
        float4 b0 = *(const float4*)(bias + lane16 * 8);
        float4 b1 = *(const float4*)(bias + lane16 * 8 + 4);
        o[0] = fmaxf(di * acc[0] + b0.x, 0.f);
        o[1] = fmaxf(di * acc[1] + b0.y, 0.f);
        o[2] = fmaxf(di * acc[2] + b0.z, 0.f);
        o[3] = fmaxf(di * acc[3] + b0.w, 0.f);
        o[4] = fmaxf(di * acc[4] + b1.x, 0.f);
        o[5] = fmaxf(di * acc[5] + b1.y, 0.f);
        o[6] = fmaxf(di * acc[6] + b1.z, 0.f);
        o[7] = fmaxf(di * acc[7] + b1.w, 0.f);
        __half2 ho[4];
#pragma unroll
        for (int q = 0; q < 4; q++) ho[q] = __floats2half2_rn(o[2 * q], o[2 * q + 1]);
        *(uint4*)(outp + (size_t)w * 128 + lane16 * 8) = *(uint4*)ho;
    }

    if (dopool) {
#pragma unroll
        for (int q = 0; q < 8; q++) {
            pS[hw][lane16 * 8 + q] = o[q];
            pM[hw][lane16 * 8 + q] = o[q];
        }
        __syncthreads();
        if (t < 128) {
            float s = 0.f, mx = 0.f;
#pragma unroll
            for (int u = 0; u < 16; u++) { s += pS[u][t]; mx = fmaxf(mx, pM[u][t]); }
            atomicAdd(&d_scr.poolsum[t], s);
            atomicMax(&d_scr.poolmax[t], __float_as_uint(mx));
        }
    }
}

// ---------------- argmax key helpers ----------------
__device__ __forceinline__ unsigned enc_f(float f) {
    unsigned u = __float_as_uint(f);
    return (u & 0x80000000u) ? ~u : (u | 0x80000000u);
}
__device__ __forceinline__ unsigned long long mkkey(float f, int j) {
    return ((unsigned long long)enc_f(f) << 32) | (unsigned long long)(0xFFFFFFFFu - (unsigned)j);
}

// ---------------- head GEMVs + inline pool final + z1 block stats ----------
__global__ __launch_bounds__(256) void gemv_heads_k(const float* __restrict__ n1W,
                                                    const float* __restrict__ n1b,
                                                    const float* __restrict__ g1,
                                                    const float* __restrict__ n2W,
                                                    const float* __restrict__ n2b,
                                                    int ncols, int halfblocks, float inv_n) {
    __shared__ float p[256];
    __shared__ float red[256];
    __shared__ unsigned long long redk[256];
    int t = threadIdx.x;
    if (t < 128) p[t] = d_scr.poolsum[t] * inv_n;
    else         p[t] = __uint_as_float(d_scr.poolmax[t - 128]);
    __syncthreads();
    int second = blockIdx.x >= halfblocks;
    int b = second ? blockIdx.x - halfblocks : blockIdx.x;
    int j4 = b * blockDim.x + t;
    bool valid = (j4 * 4 < ncols);
    float ax = 0.f, ay = 0.f, az = 0.f, aw = 0.f;
    if (valid) {
        const float* W = second ? n2W : n1W;
#pragma unroll 4
        for (int k = 0; k < 256; k++) {
            float4 w4 = *(const float4*)(W + (size_t)k * ncols + j4 * 4);
            float pv = p[k];
            ax += pv * w4.x; ay += pv * w4.y; az += pv * w4.z; aw += pv * w4.w;
        }
    }
    int j = j4 * 4;
    if (!second) {
        float4 o = make_float4(0.f, 0.f, 0.f, 0.f);
        if (valid) {
            float4 bb = *(const float4*)(n1b + j);
            float4 gg = *(const float4*)(g1 + j);
            o.x = (ax + bb.x + gg.x) * INV_TAU;
            o.y = (ay + bb.y + gg.y) * INV_TAU;
            o.z = (az + bb.z + gg.z) * INV_TAU;
            o.w = (aw + bb.w + gg.w) * INV_TAU;
            *(float4*)(d_z1 + j) = o;
        }
        float lm = valid ? fmaxf(fmaxf(o.x, o.y), fmaxf(o.z, o.w)) : -1e30f;
        red[t] = lm;
        __syncthreads();
        for (int s = 128; s > 0; s >>= 1) {
            if (t < s) red[t] = fmaxf(red[t], red[t + s]);
            __syncthreads();
        }
        float bm = red[0];
        __syncthreads();
        float ls = 0.f;
        if (valid) {
            ls = expf(o.x - bm) + expf(o.y - bm) + expf(o.z - bm) + expf(o.w - bm);
        }
        red[t] = ls;
        unsigned long long key = 0ull;
        if (valid) {
            key = mkkey(o.x, j);
            unsigned long long k1 = mkkey(o.y, j + 1); if (k1 > key) key = k1;
            unsigned long long k2 = mkkey(o.z, j + 2); if (k2 > key) key = k2;
            unsigned long long k3 = mkkey(o.w, j + 3); if (k3 > key) key = k3;
        }
        redk[t] = key;
        __syncthreads();
        for (int s = 128; s > 0; s >>= 1) {
            if (t < s) {
                red[t] += red[t + s];
                if (redk[t + s] > redk[t]) redk[t] = redk[t + s];
            }
            __syncthreads();
        }
        if (t == 0) {
            d_bm[0][b] = bm;
            d_bs[0][b] = red[0];
            d_bk[0][b] = redk[0];
        }
    } else {
        if (valid) {
            float4 bb = *(const float4*)(n2b + j);
            float4 o;
            o.x = ax + bb.x; o.y = ay + bb.y; o.z = az + bb.z; o.w = aw + bb.w;
            *(float4*)(d_l2 + j) = o;
        }
    }
}

// ---------------- merge block stats -> global M, S, argmax ----------------
__global__ void merge_k(int which, int nb) {
    __shared__ float sm[128];
    __shared__ float ss[128];
    __shared__ unsigned long long sk[128];
    int t = threadIdx.x;  // 128
    float m = (t < nb) ? d_bm[which][t] : -1e30f;
    sm[t] = m;
    __syncthreads();
    for (int s = 64; s > 0; s >>= 1) {
        if (t < s) sm[t] = fmaxf(sm[t], sm[t + s]);
        __syncthreads();
    }
    float M = sm[0];
    __syncthreads();
    float ls = (t < nb) ? d_bs[which][t] * expf(d_bm[which][t] - M) : 0.f;
    ss[t] = ls;
    sk[t] = (t < nb) ? d_bk[which][t] : 0ull;
    __syncthreads();
    for (int s = 64; s > 0; s >>= 1) {
        if (t < s) {
            ss[t] += ss[t + s];
            if (sk[t + s] > sk[t]) sk[t] = sk[t + s];
        }
        __syncthreads();
    }
    if (t == 0) {
        d_scr.zmax[which] = M;
        d_scr.S[which] = ss[0];
        int idx = (int)(0xFFFFFFFFu - (unsigned)(sk[0] & 0xFFFFFFFFull));
        d_scr.isel[which] = idx;
        if (which == 0) d_conn[idx] = 1;
    }
}

// ---------------- mask of nodes connected to i1 ----------------
__global__ void conn_k(const int* __restrict__ srcp, const int* __restrict__ dstp, int E) {
    int i1 = d_scr.isel[0];
    int e = blockIdx.x * blockDim.x + threadIdx.x;
    if (e < E) {
        int s = srcp[e], d = dstp[e];
        if (s == i1 || d == i1) { d_conn[s] = 1; d_conn[d] = 1; }
    }
}

// ---------------- fused A: [write n1_soft] || [z2 compute + block stats] ----
__global__ __launch_bounds__(256) void fused_a_k(const float* __restrict__ g2,
                                                 float* __restrict__ outp, int n, int WB) {
    __shared__ float red[256];
    __shared__ unsigned long long redk[256];
    int t = threadIdx.x;
    if ((int)blockIdx.x < WB) {
        float M = d_scr.zmax[0];
        float invS = 1.0f / d_scr.S[0];
        int j4 = blockIdx.x * 256 + t;
        int j = j4 * 4;
        if (j < n) {
            float4 z = *(const float4*)(d_z1 + j);
            float4 o;
            o.x = expf(z.x - M) * invS;
            o.y = expf(z.y - M) * invS;
            o.z = expf(z.z - M) * invS;
            o.w = expf(z.w - M) * invS;
            *(float4*)(outp + j) = o;
        }
        return;
    }
    int b = blockIdx.x - WB;
    int j4 = b * 256 + t;
    int j = j4 * 4;
    bool valid = (j < n);
    float4 z = make_float4(0.f, 0.f, 0.f, 0.f);
    if (valid) {
        float4 l = *(const float4*)(d_l2 + j);
        uchar4 cn = *(const uchar4*)(d_conn + j);
        float4 g = *(const float4*)(g2 + j);
        z.x = ((cn.x ? MASKV : l.x) + g.x) * INV_TAU;
        z.y = ((cn.y ? MASKV : l.y) + g.y) * INV_TAU;
        z.z = ((cn.z ? MASKV : l.z) + g.z) * INV_TAU;
        z.w = ((cn.w ? MASKV : l.w) + g.w) * INV_TAU;
        *(float4*)(d_z2 + j) = z;
    }
    float lm = valid ? fmaxf(fmaxf(z.x, z.y), fmaxf(z.z, z.w)) : -1e30f;
    red[t] = lm;
    __syncthreads();
    for (int s = 128; s > 0; s >>= 1) {
        if (t < s) red[t] = fmaxf(red[t], red[t + s]);
        __syncthreads();
    }
    float bm = red[0];
    __syncthreads();
    float ls = 0.f;
    if (valid) ls = expf(z.x - bm) + expf(z.y - bm) + expf(z.z - bm) + expf(z.w - bm);
    red[t] = ls;
    unsigned long long key = 0ull;
    if (valid) {
        key = mkkey(z.x, j);
        unsigned long long k1 = mkkey(z.y, j + 1); if (k1 > key) key = k1;
        unsigned long long k2 = mkkey(z.z, j + 2); if (k2 > key) key = k2;
        unsigned long long k3 = mkkey(z.w, j + 3); if (k3 > key) key = k3;
    }
    redk[t] = key;
    __syncthreads();
    for (int s = 128; s > 0; s >>= 1) {
        if (t < s) {
            red[t] += red[t + s];
            if (redk[t + s] > redk[t]) redk[t] = redk[t + s];
        }
        __syncthreads();
    }
    if (t == 0) {
        d_bm[1][b] = bm;
        d_bs[1][b] = red[0];
        d_bk[1][b] = redk[0];
    }
}

// ---------------- fused B: [esoft] || [write n2_soft] ----------------
__global__ __launch_bounds__(256) void fused_b_k(const __half* __restrict__ G,
                                                 const float* __restrict__ eW,
                                                 const float* __restrict__ eb,
                                                 const float* __restrict__ ge,
                                                 float* __restrict__ outp, int n) {
    int t = threadIdx.x;
    if (blockIdx.x == 0) {
        __shared__ float red3[3][128];
        int i1 = d_scr.isel[0];
        int i2 = d_scr.isel[1];
        if (t < 128) {
            float a = __half2float(G[(size_t)i1 * 128 + t]);
            float b = __half2float(G[(size_t)i2 * 128 + t]);
#pragma unroll
            for (int o = 0; o < 3; o++)
                red3[o][t] = a * eW[t * 3 + o] + b * eW[(128 + t) * 3 + o];
        }
        __syncthreads();
        for (int s = 64; s > 0; s >>= 1) {
            if (t < s) {
                red3[0][t] += red3[0][t + s];
                red3[1][t] += red3[1][t + s];
                red3[2][t] += red3[2][t + s];
            }
            __syncthreads();
        }
        if (t == 0) {
            float z0 = (red3[0][0] + eb[0] + ge[0]) * INV_TAU;
            float z1v = (red3[1][0] + eb[1] + ge[1]) * INV_TAU;
            float z2v = (red3[2][0] + eb[2] + ge[2]) * INV_TAU;
            float m = fmaxf(z0, fmaxf(z1v, z2v));
            float e0 = expf(z0 - m), e1 = expf(z1v - m), e2 = expf(z2v - m);
            float inv = 1.0f / (e0 + e1 + e2);
            outp[2 * n + 0] = e0 * inv;
            outp[2 * n + 1] = e1 * inv;
            outp[2 * n + 2] = e2 * inv;
            outp[2 * n + 3] = 1.0f;
        }
        return;
    }
    float M = d_scr.zmax[1];
    float invS = 1.0f / d_scr.S[1];
    int j4 = (blockIdx.x - 1) * 256 + t;
    int j = j4 * 4;
    if (j < n) {
        float4 z = *(const float4*)(d_z2 + j);
        float4 o;
        o.x = expf(z.x - M) * invS;
        o.y = expf(z.y - M) * invS;
        o.z = expf(z.z - M) * invS;
        o.w = expf(z.w - M) * invS;
        *(float4*)(outp + n + j) = o;
    }
}

// ---------------- launcher (single stream — graph-capture safe) ----------
extern "C" void kernel_launch(void* const* d_in, const int* in_sizes, int n_in,
                              void* d_out, int out_size) {
    const float* x   = (const float*)d_in[0];
    const int*   ei  = (const int*)  d_in[1];
    const float* W1  = (const float*)d_in[2];
    const float* b1  = (const float*)d_in[3];
    const float* W2  = (const float*)d_in[4];
    const float* b2  = (const float*)d_in[5];
    const float* W3  = (const float*)d_in[6];
    const float* b3  = (const float*)d_in[7];
    const float* n1W = (const float*)d_in[8];
    const float* n1b = (const float*)d_in[9];
    const float* n2W = (const float*)d_in[10];
    const float* n2b = (const float*)d_in[11];
    const float* eW  = (const float*)d_in[12];
    const float* eb  = (const float*)d_in[13];
    const float* g1  = (const float*)d_in[16];
    const float* g2  = (const float*)d_in[17];
    const float* ge  = (const float*)d_in[18];
    float* out = (float*)d_out;

    int n = in_sizes[0] / 128;
    int E = in_sizes[1] / 2;
    const int* srcp = ei;
    const int* dstp = ei + E;

    void *pc, *pconn, *pscr, *pH, *pP, *pQ;
    cudaGetSymbolAddress(&pc,    d_counts);
    cudaGetSymbolAddress(&pconn, d_conn);
    cudaGetSymbolAddress(&pscr,  d_scr);
    cudaGetSymbolAddress(&pH,    d_H);
    cudaGetSymbolAddress(&pP,    d_P);
    cudaGetSymbolAddress(&pQ,    d_Q);
    __half* H = (__half*)pH;
    __half* P = (__half*)pP;
    __half* Q = (__half*)pQ;

    const int GEMM_SMEM = 64 * XS_H * 2 + 64 * BS_W * 4;  // 51200 B
    cudaFuncSetAttribute(gemm_f16_k, cudaFuncAttributeMaxDynamicSharedMemorySize, GEMM_SMEM);

    cudaMemsetAsync(pc,    0, (size_t)n * sizeof(int), 0);
    cudaMemsetAsync(pconn, 0, (size_t)n, 0);
    cudaMemsetAsync(pscr,  0, sizeof(Scr), 0);

    int eblocks = (E + 255) / 256;
    int nb = (n + 1023) / 1024;
    degcount_k<<<eblocks, 256>>>(dstp, E);
    scan1_k<<<nb, 1024>>>(n);
    scan2_k<<<1, 128>>>(nb, n);
    scan3_k<<<nb, 1024>>>(n);
    fill_csr_k<<<eblocks, 256>>>(srcp, dstp, E);

    int gblocks = (n + 63) / 64;
    int ablocks = (n + 15) / 16;        // half-warp per node

    gemm_f16_k<<<gblocks, 256, GEMM_SMEM>>>(P, x, 1, W1, H, n);  // fused fp32->fp16
    aggregate_k<<<ablocks, 256>>>(H, b1, Q, n, 0);
    gemm_f16_k<<<gblocks, 256, GEMM_SMEM>>>(Q, 0, 0, W2, H, n);
    aggregate_k<<<ablocks, 256>>>(H, b2, P, n, 0);
    gemm_f16_k<<<gblocks, 256, GEMM_SMEM>>>(P, 0, 0, W3, H, n);
    aggregate_k<<<ablocks, 256>>>(H, b3, Q, n, 1);  // Q = gcn, pool fused

    int halfblocks = (n / 4 + 255) / 256;       // 98
    gemv_heads_k<<<2 * halfblocks, 256>>>(n1W, n1b, g1, n2W, n2b, n, halfblocks,
                                          1.0f / (float)n);
    merge_k<<<1, 128>>>(0, halfblocks);
    conn_k<<<eblocks, 256>>>(srcp, dstp, E);

    int WB = (n + 1023) / 1024;                  // 98
    fused_a_k<<<2 * WB, 256>>>(g2, out, n, WB);
    merge_k<<<1, 128>>>(1, WB);
    fused_b_k<<<WB + 1, 256>>>(Q, eW, eb, ge, out, n);
}

// round 14
// speedup vs baseline: 1.4413x; 1.0084x over previous
#include <cuda_runtime.h>
#include <cuda_bf16.h>
#include <cuda_fp16.h>

#define NMAX 100000
#define EMAX 1600000
#define MASKV (-1000000000.0f)
#define INV_TAU 2.0f

// ---------------- device scratch (static allocation only) ----------------
struct Scr {
    float poolsum[128];
    unsigned int poolmax[128];
    float zmax[2];
    float S[2];
    int isel[2];
};

__device__ __half d_H[NMAX * 128];   // GEMM output (pre-aggregation)
__device__ __half d_P[NMAX * 128];   // activation ping
__device__ __half d_Q[NMAX * 128];   // activation pong
__device__ int    d_counts[NMAX];
__device__ int    d_rowstart[NMAX + 1];
__device__ int    d_cursor[NMAX];
__device__ int    d_csr[EMAX];
__device__ float  d_dinv[NMAX];
__device__ float  d_z1[NMAX];
__device__ float  d_l2[NMAX];
__device__ float  d_z2[NMAX];
__device__ unsigned char d_conn[NMAX];
__device__ int    d_bsum[128];
__device__ int    d_boff[128];
__device__ float  d_bm[2][128];
__device__ float  d_bs[2][128];
__device__ unsigned long long d_bk[2][128];
__device__ Scr    d_scr;

// ---------------- CSR build ----------------
__global__ void degcount_k(const int* __restrict__ dstp, int E) {
    int e = blockIdx.x * blockDim.x + threadIdx.x;
    if (e < E) atomicAdd(&d_counts[dstp[e]], 1);
}

__global__ void scan1_k(int n) {
    __shared__ int sm[1024];
    int t = threadIdx.x;
    int i = blockIdx.x * 1024 + t;
    int v = (i < n) ? d_counts[i] : 0;
    sm[t] = v;
    __syncthreads();
    for (int s = 512; s > 0; s >>= 1) {
        if (t < s) sm[t] += sm[t + s];
        __syncthreads();
    }
    if (t == 0) d_bsum[blockIdx.x] = sm[0];
}

__global__ void scan2_k(int nb, int n) {
    __shared__ int sm[128];
    int t = threadIdx.x;
    int v = (t < nb) ? d_bsum[t] : 0;
    sm[t] = v;
    __syncthreads();
    for (int d = 1; d < 128; d <<= 1) {
        int add = (t >= d) ? sm[t - d] : 0;
        __syncthreads();
        sm[t] += add;
        __syncthreads();
    }
    if (t < nb) d_boff[t] = sm[t] - v;
    if (t == nb - 1) d_rowstart[n] = sm[t];
}

__global__ void scan3_k(int n) {
    __shared__ int sm[1024];
    int t = threadIdx.x;
    int i = blockIdx.x * 1024 + t;
    int v = (i < n) ? d_counts[i] : 0;
    sm[t] = v;
    __syncthreads();
    for (int d = 1; d < 1024; d <<= 1) {
        int add = (t >= d) ? sm[t - d] : 0;
        __syncthreads();
        sm[t] += add;
        __syncthreads();
    }
    if (i < n) {
        int excl = sm[t] - v + d_boff[blockIdx.x];
        d_rowstart[i] = excl;
        d_cursor[i]   = excl;
        d_dinv[i]     = rsqrtf((float)v + 1.0f);
    }
}

__global__ void fill_csr_k(const int* __restrict__ srcp, const int* __restrict__ dstp, int E) {
    int e = blockIdx.x * blockDim.x + threadIdx.x;
    if (e < E) {
        int d = dstp[e];
        int pos = atomicAdd(&d_cursor[d], 1);
        d_csr[pos] = srcp[e];
    }
}

// ---------------- fp16 tensor-core GEMM: Hout = fp16(dinv * (X @ W)) ------
// 128-row tiles; xf32 != 0: X32 is the fp32 input (layer 1, converts in-load).
#define XS_H 136
#define BS_W 132
#define GROWS 128

__device__ __forceinline__ void mma_f16(float* d,
                                        unsigned a0, unsigned a1, unsigned a2, unsigned a3,
                                        unsigned b0, unsigned b1) {
    asm volatile("mma.sync.aligned.m16n8k16.row.col.f32.f16.f16.f32 "
                 "{%0,%1,%2,%3}, {%4,%5,%6,%7}, {%8,%9}, {%0,%1,%2,%3};"
                 : "+f"(d[0]), "+f"(d[1]), "+f"(d[2]), "+f"(d[3])
                 : "r"(a0), "r"(a1), "r"(a2), "r"(a3), "r"(b0), "r"(b1));
}

__global__ __launch_bounds__(256) void gemm_f16_k(const __half* __restrict__ X,
                                                  const float* __restrict__ X32,
                                                  int xf32,
                                                  const float* __restrict__ W,
                                                  __half* __restrict__ Hout, int n) {
    extern __shared__ char shraw[];
    __half*  xs = (__half*)shraw;                        // GROWS x XS_H halfs
    __half2* bs = (__half2*)(shraw + GROWS * XS_H * 2);  // 64 x BS_W half2

    int t = threadIdx.x;
    int row0 = blockIdx.x * GROWS;
    int nr = n - row0; if (nr > GROWS) nr = GROWS;

    for (int i = t; i < 64 * 128; i += 256) {
        int k2 = i >> 7, nn = i & 127;
        float w0 = W[(size_t)(2 * k2) * 128 + nn];
        float w1 = W[(size_t)(2 * k2 + 1) * 128 + nn];
        bs[k2 * BS_W + nn] = __floats2half2_rn(w0, w1);
    }
    if (xf32) {
        for (int i = t; i < nr * 32; i += 256) {
            int rr = i >> 5, c4 = i & 31;
            float4 v = *(const float4*)(X32 + (size_t)(row0 + rr) * 128 + c4 * 4);
            __half2 a = __floats2half2_rn(v.x, v.y);
            __half2 b = __floats2half2_rn(v.z, v.w);
            *(uint2*)(xs + rr * XS_H + c4 * 4) = make_uint2(*(unsigned*)&a, *(unsigned*)&b);
        }
    } else {
        for (int i = t; i < nr * 16; i += 256) {
            int rr = i >> 4, c8 = i & 15;
            uint4 v = *(const uint4*)(X + (size_t)(row0 + rr) * 128 + c8 * 8);
            *(uint4*)(xs + rr * XS_H + c8 * 8) = v;
        }
    }
    __syncthreads();

    int lane = t & 31, wid = t >> 5;
    int wm = wid & 3, wn = wid >> 2;     // 4 m-tiles x 2 n-tiles
    int m0 = wm * 32, n0 = wn * 64;      // warp tile 32 rows x 64 cols
    int r = lane >> 2, c = lane & 3;

    float acc[2][8][4];
#pragma unroll
    for (int mi = 0; mi < 2; mi++)
#pragma unroll
        for (int nj = 0; nj < 8; nj++)
#pragma unroll
            for (int q = 0; q < 4; q++) acc[mi][nj][q] = 0.f;

#pragma unroll
    for (int k0 = 0; k0 < 8; k0++) {
        unsigned a[2][4];
#pragma unroll
        for (int mi = 0; mi < 2; mi++) {
            const __half* xb = xs + (m0 + mi * 16 + r) * XS_H + k0 * 16 + 2 * c;
            a[mi][0] = *(const unsigned*)(xb);
            a[mi][1] = *(const unsigned*)(xb + 8 * XS_H);
            a[mi][2] = *(const unsigned*)(xb + 8);
            a[mi][3] = *(const unsigned*)(xb + 8 * XS_H + 8);
        }
#pragma unroll
        for (int nj = 0; nj < 8; nj++) {
            const __half2* bb = bs + (k0 * 8 + c) * BS_W + n0 + nj * 8 + r;
            unsigned b0 = *(const unsigned*)(bb);
            unsigned b1 = *(const unsigned*)(bb + 4 * BS_W);
#pragma unroll
            for (int mi = 0; mi < 2; mi++)
                mma_f16(acc[mi][nj], a[mi][0], a[mi][1], a[mi][2], a[mi][3], b0, b1);
        }
    }

#pragma unroll
    for (int mi = 0; mi < 2; mi++) {
        int rloc = m0 + mi * 16 + r;
        float s0 = 0.f, s1 = 0.f;
        if (rloc < nr)     s0 = d_dinv[row0 + rloc];
        if (rloc + 8 < nr) s1 = d_dinv[row0 + rloc + 8];
#pragma unroll
        for (int nj = 0; nj < 8; nj++) {
            int col = n0 + nj * 8 + 2 * c;
            if (rloc < nr) {
                __half2 h = __floats2half2_rn(acc[mi][nj][0] * s0, acc[mi][nj][1] * s0);
                *(__half2*)(Hout + (size_t)(row0 + rloc) * 128 + col) = h;
            }
            if (rloc + 8 < nr) {
                __half2 h = __floats2half2_rn(acc[mi][nj][2] * s1, acc[mi][nj][3] * s1);
                *(__half2*)(Hout + (size_t)(row0 + rloc + 8) * 128 + col) = h;
            }
        }
    }
}

// ---------------- aggregation: half-warp per node, LOCKSTEP halves --------
__global__ __launch_bounds__(256) void aggregate_k(const __half* __restrict__ H,
                                                   const float* __restrict__ bias,
                                                   __half* __restrict__ outp, int n,
                                                   int dopool) {
    __shared__ float pS[16][128];
    __shared__ float pM[16][128];
    int t = threadIdx.x;
    int hw = t >> 4;
    int lane16 = t & 15;
    int w = blockIdx.x * 16 + hw;
    unsigned hmask = 0xFFFFu << (t & 16);
    bool active = (w < n);

    int beg = 0, cnt = 0;
    if (active) {
        beg = d_rowstart[w];
        cnt = d_rowstart[w + 1] - beg;
    }
    int mc = cnt;
    int other = __shfl_xor_sync(0xffffffffu, cnt, 16);
    if (other > mc) mc = other;

    float acc[8];
#pragma unroll
    for (int q = 0; q < 8; q++) acc[q] = 0.f;
    const __half* Hl = H + lane16 * 8;

    for (int base = 0; base < mc; base += 16) {
        int wcnt = mc - base; if (wcnt > 16) wcnt = 16;
        int myrem = cnt - base;
        int idx = 0;
        if (lane16 < myrem) idx = d_csr[beg + base + lane16];
        uint4 h[4];
#pragma unroll
        for (int u = 0; u < 4; u++) {
            int s = __shfl_sync(hmask, idx, u, 16);
            h[u] = (u < myrem) ? *(const uint4*)(Hl + (size_t)s * 128)
                               : make_uint4(0u, 0u, 0u, 0u);
        }
        for (int j0 = 0; j0 < wcnt; j0 += 4) {
            uint4 h2[4];
#pragma unroll
            for (int u = 0; u < 4; u++) {
                int jj = j0 + 4 + u;
                int s = __shfl_sync(hmask, idx, jj & 15, 16);
                h2[u] = (jj < myrem && jj < 16) ? *(const uint4*)(Hl + (size_t)s * 128)
                                                : make_uint4(0u, 0u, 0u, 0u);
            }
#pragma unroll
            for (int u = 0; u < 4; u++) {
                const __half2* p2 = (const __half2*)&h[u];
#pragma unroll
                for (int q = 0; q < 4; q++) {
                    float2 f = __half22float2(p2[q]);
                    acc[2 * q]     += f.x;
                    acc[2 * q + 1] += f.y;
                }
            }
#pragma unroll
            for (int u = 0; u < 4; u++) h[u] = h2[u];
        }
    }

    float o[8];
#pragma unroll
    for (int q = 0; q < 8; q++) o[q] = 0.f;

    if (active) {
        uint4 hs = *(const uint4*)(Hl + (size_t)w * 128);
        const __half2* p2 = (const __half2*)&hs;
#pragma unroll
        for (int q = 0; q < 4; q++) {
            float2 f = __half22float2(p2[q]);
            acc[2 * q]     += f.x;
            acc[2 * q + 1] += f.y;
        }
        float di = d_dinv[w];
        float4 b0 = *(const float4*)(bias + lane16 * 8);
        float4 b1 = *(const float4*)(bias + lane16 * 8 + 4);
        o[0] = fmaxf(di * acc[0] + b0.x, 0.f);
        o[1] = fmaxf(di * acc[1] + b0.y, 0.f);
        o[2] = fmaxf(di * acc[2] + b0.z, 0.f);
        o[3] = fmaxf(di * acc[3] + b0.w, 0.f);
        o[4] = fmaxf(di * acc[4] + b1.x, 0.f);
        o[5] = fmaxf(di * acc[5] + b1.y, 0.f);
        o[6] = fmaxf(di * acc[6] + b1.z, 0.f);
        o[7] = fmaxf(di * acc[7] + b1.w, 0.f);
        __half2 ho[4];
#pragma unroll
        for (int q = 0; q < 4; q++) ho[q] = __floats2half2_rn(o[2 * q], o[2 * q + 1]);
        *(uint4*)(outp + (size_t)w * 128 + lane16 * 8) = *(uint4*)ho;
    }

    if (dopool) {
#pragma unroll
        for (int q = 0; q < 8; q++) {
            pS[hw][lane16 * 8 + q] = o[q];
            pM[hw][lane16 * 8 + q] = o[q];
        }
        __syncthreads();
        if (t < 128) {
            float s = 0.f, mx = 0.f;
#pragma unroll
            for (int u = 0; u < 16; u++) { s += pS[u][t]; mx = fmaxf(mx, pM[u][t]); }
            atomicAdd(&d_scr.poolsum[t], s);
            atomicMax(&d_scr.poolmax[t], __float_as_uint(mx));
        }
    }
}

// ---------------- argmax key helpers ----------------
__device__ __forceinline__ unsigned enc_f(float f) {
    unsigned u = __float_as_uint(f);
    return (u & 0x80000000u) ? ~u : (u | 0x80000000u);
}
__device__ __forceinline__ unsigned long long mkkey(float f, int j) {
    return ((unsigned long long)enc_f(f) << 32) | (unsigned long long)(0xFFFFFFFFu - (unsigned)j);
}

// ---------------- head GEMVs + inline pool final + z1 block stats ----------
__global__ __launch_bounds__(256) void gemv_heads_k(const float* __restrict__ n1W,
                                                    const float* __restrict__ n1b,
                                                    const float* __restrict__ g1,
                                                    const float* __restrict__ n2W,
                                                    const float* __restrict__ n2b,
                                                    int ncols, int halfblocks, float inv_n) {
    __shared__ float p[256];
    __shared__ float red[256];
    __shared__ unsigned long long redk[256];
    int t = threadIdx.x;
    if (t < 128) p[t] = d_scr.poolsum[t] * inv_n;
    else         p[t] = __uint_as_float(d_scr.poolmax[t - 128]);
    __syncthreads();
    int second = blockIdx.x >= halfblocks;
    int b = second ? blockIdx.x - halfblocks : blockIdx.x;
    int j4 = b * blockDim.x + t;
    bool valid = (j4 * 4 < ncols);
    float ax = 0.f, ay = 0.f, az = 0.f, aw = 0.f;
    if (valid) {
        const float* W = second ? n2W : n1W;
#pragma unroll 4
        for (int k = 0; k < 256; k++) {
            float4 w4 = *(const float4*)(W + (size_t)k * ncols + j4 * 4);
            float pv = p[k];
            ax += pv * w4.x; ay += pv * w4.y; az += pv * w4.z; aw += pv * w4.w;
        }
    }
    int j = j4 * 4;
    if (!second) {
        float4 o = make_float4(0.f, 0.f, 0.f, 0.f);
        if (valid) {
            float4 bb = *(const float4*)(n1b + j);
            float4 gg = *(const float4*)(g1 + j);
            o.x = (ax + bb.x + gg.x) * INV_TAU;
            o.y = (ay + bb.y + gg.y) * INV_TAU;
            o.z = (az + bb.z + gg.z) * INV_TAU;
            o.w = (aw + bb.w + gg.w) * INV_TAU;
            *(float4*)(d_z1 + j) = o;
        }
        float lm = valid ? fmaxf(fmaxf(o.x, o.y), fmaxf(o.z, o.w)) : -1e30f;
        red[t] = lm;
        __syncthreads();
        for (int s = 128; s > 0; s >>= 1) {
            if (t < s) red[t] = fmaxf(red[t], red[t + s]);
            __syncthreads();
        }
        float bm = red[0];
        __syncthreads();
        float ls = 0.f;
        if (valid) {
            ls = expf(o.x - bm) + expf(o.y - bm) + expf(o.z - bm) + expf(o.w - bm);
        }
        red[t] = ls;
        unsigned long long key = 0ull;
        if (valid) {
            key = mkkey(o.x, j);
            unsigned long long k1 = mkkey(o.y, j + 1); if (k1 > key) key = k1;
            unsigned long long k2 = mkkey(o.z, j + 2); if (k2 > key) key = k2;
            unsigned long long k3 = mkkey(o.w, j + 3); if (k3 > key) key = k3;
        }
        redk[t] = key;
        __syncthreads();
        for (int s = 128; s > 0; s >>= 1) {
            if (t < s) {
                red[t] += red[t + s];
                if (redk[t + s] > redk[t]) redk[t] = redk[t + s];
            }
            __syncthreads();
        }
        if (t == 0) {
            d_bm[0][b] = bm;
            d_bs[0][b] = red[0];
            d_bk[0][b] = redk[0];
        }
    } else {
        if (valid) {
            float4 bb = *(const float4*)(n2b + j);
            float4 o;
            o.x = ax + bb.x; o.y = ay + bb.y; o.z = az + bb.z; o.w = aw + bb.w;
            *(float4*)(d_l2 + j) = o;
        }
    }
}

// ---------------- merge block stats -> global M, S, argmax ----------------
__global__ void merge_k(int which, int nb) {
    __shared__ float sm[128];
    __shared__ float ss[128];
    __shared__ unsigned long long sk[128];
    int t = threadIdx.x;  // 128
    float m = (t < nb) ? d_bm[which][t] : -1e30f;
    sm[t] = m;
    __syncthreads();
    for (int s = 64; s > 0; s >>= 1) {
        if (t < s) sm[t] = fmaxf(sm[t], sm[t + s]);
        __syncthreads();
    }
    float M = sm[0];
    __syncthreads();
    float ls = (t < nb) ? d_bs[which][t] * expf(d_bm[which][t] - M) : 0.f;
    ss[t] = ls;
    sk[t] = (t < nb) ? d_bk[which][t] : 0ull;
    __syncthreads();
    for (int s = 64; s > 0; s >>= 1) {
        if (t < s) {
            ss[t] += ss[t + s];
            if (sk[t + s] > sk[t]) sk[t] = sk[t + s];
        }
        __syncthreads();
    }
    if (t == 0) {
        d_scr.zmax[which] = M;
        d_scr.S[which] = ss[0];
        int idx = (int)(0xFFFFFFFFu - (unsigned)(sk[0] & 0xFFFFFFFFull));
        d_scr.isel[which] = idx;
        if (which == 0) d_conn[idx] = 1;
    }
}

// ---------------- mask of nodes connected to i1 ----------------
__global__ void conn_k(const int* __restrict__ srcp, const int* __restrict__ dstp, int E) {
    int i1 = d_scr.isel[0];
    int e = blockIdx.x * blockDim.x + threadIdx.x;
    if (e < E) {
        int s = srcp[e], d = dstp[e];
        if (s == i1 || d == i1) { d_conn[s] = 1; d_conn[d] = 1; }
    }
}

// ---------------- fused A: [write n1_soft] || [z2 compute + block stats] ----
__global__ __launch_bounds__(256) void fused_a_k(const float* __restrict__ g2,
                                                 float* __restrict__ outp, int n, int WB) {
    __shared__ float red[256];
    __shared__ unsigned long long redk[256];
    int t = threadIdx.x;
    if ((int)blockIdx.x < WB) {
        float M = d_scr.zmax[0];
        float invS = 1.0f / d_scr.S[0];
        int j4 = blockIdx.x * 256 + t;
        int j = j4 * 4;
        if (j < n) {
            float4 z = *(const float4*)(d_z1 + j);
            float4 o;
            o.x = expf(z.x - M) * invS;
            o.y = expf(z.y - M) * invS;
            o.z = expf(z.z - M) * invS;
            o.w = expf(z.w - M) * invS;
            *(float4*)(outp + j) = o;
        }
        return;
    }
    int b = blockIdx.x - WB;
    int j4 = b * 256 + t;
    int j = j4 * 4;
    bool valid = (j < n);
    float4 z = make_float4(0.f, 0.f, 0.f, 0.f);
    if (valid) {
        float4 l = *(const float4*)(d_l2 + j);
        uchar4 cn = *(const uchar4*)(d_conn + j);
        float4 g = *(const float4*)(g2 + j);
        z.x = ((cn.x ? MASKV : l.x) + g.x) * INV_TAU;
        z.y = ((cn.y ? MASKV : l.y) + g.y) * INV_TAU;
        z.z = ((cn.z ? MASKV : l.z) + g.z) * INV_TAU;
        z.w = ((cn.w ? MASKV : l.w) + g.w) * INV_TAU;
        *(float4*)(d_z2 + j) = z;
    }
    float lm = valid ? fmaxf(fmaxf(z.x, z.y), fmaxf(z.z, z.w)) : -1e30f;
    red[t] = lm;
    __syncthreads();
    for (int s = 128; s > 0; s >>= 1) {
        if (t < s) red[t] = fmaxf(red[t], red[t + s]);
        __syncthreads();
    }
    float bm = red[0];
    __syncthreads();
    float ls = 0.f;
    if (valid) ls = expf(z.x - bm) + expf(z.y - bm) + expf(z.z - bm) + expf(z.w - bm);
    red[t] = ls;
    unsigned long long key = 0ull;
    if (valid) {
        key = mkkey(z.x, j);
        unsigned long long k1 = mkkey(z.y, j + 1); if (k1 > key) key = k1;
        unsigned long long k2 = mkkey(z.z, j + 2); if (k2 > key) key = k2;
        unsigned long long k3 = mkkey(z.w, j + 3); if (k3 > key) key = k3;
    }
    redk[t] = key;
    __syncthreads();
    for (int s = 128; s > 0; s >>= 1) {
        if (t < s) {
            red[t] += red[t + s];
            if (redk[t + s] > redk[t]) redk[t] = redk[t + s];
        }
        __syncthreads();
    }
    if (t == 0) {
        d_bm[1][b] = bm;
        d_bs[1][b] = red[0];
        d_bk[1][b] = redk[0];
    }
}

// ---------------- fused B: [esoft] || [write n2_soft] ----------------
__global__ __launch_bounds__(256) void fused_b_k(const __half* __restrict__ G,
                                                 const float* __restrict__ eW,
                                                 const float* __restrict__ eb,
                                                 const float* __restrict__ ge,
                                                 float* __restrict__ outp, int n) {
    int t = threadIdx.x;
    if (blockIdx.x == 0) {
        __shared__ float red3[3][128];
        int i1 = d_scr.isel[0];
        int i2 = d_scr.isel[1];
        if (t < 128) {
            float a = __half2float(G[(size_t)i1 * 128 + t]);
            float b = __half2float(G[(size_t)i2 * 128 + t]);
#pragma unroll
            for (int o = 0; o < 3; o++)
                red3[o][t] = a * eW[t * 3 + o] + b * eW[(128 + t) * 3 + o];
        }
        __syncthreads();
        for (int s = 64; s > 0; s >>= 1) {
            if (t < s) {
                red3[0][t] += red3[0][t + s];
                red3[1][t] += red3[1][t + s];
                red3[2][t] += red3[2][t + s];
            }
            __syncthreads();
        }
        if (t == 0) {
            float z0 = (red3[0][0] + eb[0] + ge[0]) * INV_TAU;
            float z1v = (red3[1][0] + eb[1] + ge[1]) * INV_TAU;
            float z2v = (red3[2][0] + eb[2] + ge[2]) * INV_TAU;
            float m = fmaxf(z0, fmaxf(z1v, z2v));
            float e0 = expf(z0 - m), e1 = expf(z1v - m), e2 = expf(z2v - m);
            float inv = 1.0f / (e0 + e1 + e2);
            outp[2 * n + 0] = e0 * inv;
            outp[2 * n + 1] = e1 * inv;
            outp[2 * n + 2] = e2 * inv;
            outp[2 * n + 3] = 1.0f;
        }
        return;
    }
    float M = d_scr.zmax[1];
    float invS = 1.0f / d_scr.S[1];
    int j4 = (blockIdx.x - 1) * 256 + t;
    int j = j4 * 4;
    if (j < n) {
        float4 z = *(const float4*)(d_z2 + j);
        float4 o;
        o.x = expf(z.x - M) * invS;
        o.y = expf(z.y - M) * invS;
        o.z = expf(z.z - M) * invS;
        o.w = expf(z.w - M) * invS;
        *(float4*)(outp + n + j) = o;
    }
}

// ---------------- launcher (single stream — graph-capture safe) ----------
extern "C" void kernel_launch(void* const* d_in, const int* in_sizes, int n_in,
                              void* d_out, int out_size) {
    const float* x   = (const float*)d_in[0];
    const int*   ei  = (const int*)  d_in[1];
    const float* W1  = (const float*)d_in[2];
    const float* b1  = (const float*)d_in[3];
    const float* W2  = (const float*)d_in[4];
    const float* b2  = (const float*)d_in[5];
    const float* W3  = (const float*)d_in[6];
    const float* b3  = (const float*)d_in[7];
    const float* n1W = (const float*)d_in[8];
    const float* n1b = (const float*)d_in[9];
    const float* n2W = (const float*)d_in[10];
    const float* n2b = (const float*)d_in[11];
    const float* eW  = (const float*)d_in[12];
    const float* eb  = (const float*)d_in[13];
    const float* g1  = (const float*)d_in[16];
    const float* g2  = (const float*)d_in[17];
    const float* ge  = (const float*)d_in[18];
    float* out = (float*)d_out;

    int n = in_sizes[0] / 128;
    int E = in_sizes[1] / 2;
    const int* srcp = ei;
    const int* dstp = ei + E;

    void *pc, *pconn, *pscr, *pH, *pP, *pQ;
    cudaGetSymbolAddress(&pc,    d_counts);
    cudaGetSymbolAddress(&pconn, d_conn);
    cudaGetSymbolAddress(&pscr,  d_scr);
    cudaGetSymbolAddress(&pH,    d_H);
    cudaGetSymbolAddress(&pP,    d_P);
    cudaGetSymbolAddress(&pQ,    d_Q);
    __half* H = (__half*)pH;
    __half* P = (__half*)pP;
    __half* Q = (__half*)pQ;

    const int GEMM_SMEM = GROWS * XS_H * 2 + 64 * BS_W * 4;  // 34816+33792=68608 B
    cudaFuncSetAttribute(gemm_f16_k, cudaFuncAttributeMaxDynamicSharedMemorySize, GEMM_SMEM);

    int eblocks = (E + 255) / 256;
    int nb = (n + 1023) / 1024;

    cudaMemsetAsync(pc, 0, (size_t)n * sizeof(int), 0);
    degcount_k<<<eblocks, 256>>>(dstp, E);
    scan1_k<<<nb, 1024>>>(n);
    scan2_k<<<1, 128>>>(nb, n);
    scan3_k<<<nb, 1024>>>(n);

    int gblocks = (n + GROWS - 1) / GROWS;
    int ablocks = (n + 15) / 16;        // half-warp per node

    // GEMM1 needs only dinv -> launch before fill (serial stream; shifts ncu slot)
    gemm_f16_k<<<gblocks, 256, GEMM_SMEM>>>(P, x, 1, W1, H, n);  // fused fp32->fp16
    fill_csr_k<<<eblocks, 256>>>(srcp, dstp, E);

    cudaMemsetAsync(pscr, 0, sizeof(Scr), 0);
    aggregate_k<<<ablocks, 256>>>(H, b1, Q, n, 0);
    gemm_f16_k<<<gblocks, 256, GEMM_SMEM>>>(Q, 0, 0, W2, H, n);
    aggregate_k<<<ablocks, 256>>>(H, b2, P, n, 0);
    gemm_f16_k<<<gblocks, 256, GEMM_SMEM>>>(P, 0, 0, W3, H, n);
    aggregate_k<<<ablocks, 256>>>(H, b3, Q, n, 1);  // Q = gcn, pool fused

    cudaMemsetAsync(pconn, 0, (size_t)n, 0);
    int halfblocks = (n / 4 + 255) / 256;       // 98
    gemv_heads_k<<<2 * halfblocks, 256>>>(n1W, n1b, g1, n2W, n2b, n, halfblocks,
                                          1.0f / (float)n);
    merge_k<<<1, 128>>>(0, halfblocks);
    conn_k<<<eblocks, 256>>>(srcp, dstp, E);

    int WB = (n + 1023) / 1024;                  // 98
    fused_a_k<<<2 * WB, 256>>>(g2, out, n, WB);
    merge_k<<<1, 128>>>(1, WB);
    fused_b_k<<<WB + 1, 256>>>(Q, eW, eb, ge, out, n);
}

// round 15
// speedup vs baseline: 1.7039x; 1.1822x over previous
#include <cuda_runtime.h>
#include <cuda_bf16.h>
#include <cuda_fp16.h>

#define NMAX 100000
#define EMAX 1600000
#define MASKV (-1000000000.0f)
#define INV_TAU 2.0f

// ---------------- device scratch (static allocation only) ----------------
struct Scr {
    float poolsum[128];
    unsigned int poolmax[128];
    float zmax[2];
    float S[2];
    int isel[2];
};

__device__ __half d_H[NMAX * 128];   // GEMM output (pre-aggregation)
__device__ __half d_P[NMAX * 128];   // activation ping
__device__ __half d_Q[NMAX * 128];   // activation pong
__device__ int    d_counts[NMAX];
__device__ int    d_rowstart[NMAX + 1];
__device__ int    d_cursor[NMAX];
__device__ int    d_csr[EMAX];
__device__ float  d_dinv[NMAX];
__device__ float  d_z1[NMAX];
__device__ float  d_l2[NMAX];
__device__ float  d_z2[NMAX];
__device__ unsigned char d_conn[NMAX];
__device__ int    d_bsum[128];
__device__ int    d_boff[128];
__device__ float  d_bm[2][512];
__device__ float  d_bs[2][512];
__device__ unsigned long long d_bk[2][512];
__device__ Scr    d_scr;

// ---------------- CSR build ----------------
__global__ void degcount_k(const int* __restrict__ dstp, int E) {
    int e = blockIdx.x * blockDim.x + threadIdx.x;
    if (e < E) atomicAdd(&d_counts[dstp[e]], 1);
}

__global__ void scan1_k(int n) {
    __shared__ int sm[1024];
    int t = threadIdx.x;
    int i = blockIdx.x * 1024 + t;
    int v = (i < n) ? d_counts[i] : 0;
    sm[t] = v;
    __syncthreads();
    for (int s = 512; s > 0; s >>= 1) {
        if (t < s) sm[t] += sm[t + s];
        __syncthreads();
    }
    if (t == 0) d_bsum[blockIdx.x] = sm[0];
}

__global__ void scan2_k(int nb, int n) {
    __shared__ int sm[128];
    int t = threadIdx.x;
    int v = (t < nb) ? d_bsum[t] : 0;
    sm[t] = v;
    __syncthreads();
    for (int d = 1; d < 128; d <<= 1) {
        int add = (t >= d) ? sm[t - d] : 0;
        __syncthreads();
        sm[t] += add;
        __syncthreads();
    }
    if (t < nb) d_boff[t] = sm[t] - v;
    if (t == nb - 1) d_rowstart[n] = sm[t];
}

__global__ void scan3_k(int n) {
    __shared__ int sm[1024];
    int t = threadIdx.x;
    int i = blockIdx.x * 1024 + t;
    int v = (i < n) ? d_counts[i] : 0;
    sm[t] = v;
    __syncthreads();
    for (int d = 1; d < 1024; d <<= 1) {
        int add = (t >= d) ? sm[t - d] : 0;
        __syncthreads();
        sm[t] += add;
        __syncthreads();
    }
    if (i < n) {
        int excl = sm[t] - v + d_boff[blockIdx.x];
        d_rowstart[i] = excl;
        d_cursor[i]   = excl;
        d_dinv[i]     = rsqrtf((float)v + 1.0f);
    }
}

__global__ void fill_csr_k(const int* __restrict__ srcp, const int* __restrict__ dstp, int E) {
    int e = blockIdx.x * blockDim.x + threadIdx.x;
    if (e < E) {
        int d = dstp[e];
        int pos = atomicAdd(&d_cursor[d], 1);
        d_csr[pos] = srcp[e];
    }
}

// ---------------- fp16 tensor-core GEMM: Hout = fp16(dinv * (X @ W)) ------
#define XS_H 136
#define BS_W 132
#define GROWS 128

__device__ __forceinline__ void mma_f16(float* d,
                                        unsigned a0, unsigned a1, unsigned a2, unsigned a3,
                                        unsigned b0, unsigned b1) {
    asm volatile("mma.sync.aligned.m16n8k16.row.col.f32.f16.f16.f32 "
                 "{%0,%1,%2,%3}, {%4,%5,%6,%7}, {%8,%9}, {%0,%1,%2,%3};"
                 : "+f"(d[0]), "+f"(d[1]), "+f"(d[2]), "+f"(d[3])
                 : "r"(a0), "r"(a1), "r"(a2), "r"(a3), "r"(b0), "r"(b1));
}

__global__ __launch_bounds__(256) void gemm_f16_k(const __half* __restrict__ X,
                                                  const float* __restrict__ X32,
                                                  int xf32,
                                                  const float* __restrict__ W,
                                                  __half* __restrict__ Hout, int n) {
    extern __shared__ char shraw[];
    __half*  xs = (__half*)shraw;                        // GROWS x XS_H halfs
    __half2* bs = (__half2*)(shraw + GROWS * XS_H * 2);  // 64 x BS_W half2

    int t = threadIdx.x;
    int row0 = blockIdx.x * GROWS;
    int nr = n - row0; if (nr > GROWS) nr = GROWS;

    for (int i = t; i < 64 * 128; i += 256) {
        int k2 = i >> 7, nn = i & 127;
        float w0 = W[(size_t)(2 * k2) * 128 + nn];
        float w1 = W[(size_t)(2 * k2 + 1) * 128 + nn];
        bs[k2 * BS_W + nn] = __floats2half2_rn(w0, w1);
    }
    if (xf32) {
        for (int i = t; i < nr * 32; i += 256) {
            int rr = i >> 5, c4 = i & 31;
            float4 v = *(const float4*)(X32 + (size_t)(row0 + rr) * 128 + c4 * 4);
            __half2 a = __floats2half2_rn(v.x, v.y);
            __half2 b = __floats2half2_rn(v.z, v.w);
            *(uint2*)(xs + rr * XS_H + c4 * 4) = make_uint2(*(unsigned*)&a, *(unsigned*)&b);
        }
    } else {
        for (int i = t; i < nr * 16; i += 256) {
            int rr = i >> 4, c8 = i & 15;
            uint4 v = *(const uint4*)(X + (size_t)(row0 + rr) * 128 + c8 * 8);
            *(uint4*)(xs + rr * XS_H + c8 * 8) = v;
        }
    }
    __syncthreads();

    int lane = t & 31, wid = t >> 5;
    int wm = wid & 3, wn = wid >> 2;
    int m0 = wm * 32, n0 = wn * 64;
    int r = lane >> 2, c = lane & 3;

    float acc[2][8][4];
#pragma unroll
    for (int mi = 0; mi < 2; mi++)
#pragma unroll
        for (int nj = 0; nj < 8; nj++)
#pragma unroll
            for (int q = 0; q < 4; q++) acc[mi][nj][q] = 0.f;

#pragma unroll
    for (int k0 = 0; k0 < 8; k0++) {
        unsigned a[2][4];
#pragma unroll
        for (int mi = 0; mi < 2; mi++) {
            const __half* xb = xs + (m0 + mi * 16 + r) * XS_H + k0 * 16 + 2 * c;
            a[mi][0] = *(const unsigned*)(xb);
            a[mi][1] = *(const unsigned*)(xb + 8 * XS_H);
            a[mi][2] = *(const unsigned*)(xb + 8);
            a[mi][3] = *(const unsigned*)(xb + 8 * XS_H + 8);
        }
#pragma unroll
        for (int nj = 0; nj < 8; nj++) {
            const __half2* bb = bs + (k0 * 8 + c) * BS_W + n0 + nj * 8 + r;
            unsigned b0 = *(const unsigned*)(bb);
            unsigned b1 = *(const unsigned*)(bb + 4 * BS_W);
#pragma unroll
            for (int mi = 0; mi < 2; mi++)
                mma_f16(acc[mi][nj], a[mi][0], a[mi][1], a[mi][2], a[mi][3], b0, b1);
        }
    }

#pragma unroll
    for (int mi = 0; mi < 2; mi++) {
        int rloc = m0 + mi * 16 + r;
        float s0 = 0.f, s1 = 0.f;
        if (rloc < nr)     s0 = d_dinv[row0 + rloc];
        if (rloc + 8 < nr) s1 = d_dinv[row0 + rloc + 8];
#pragma unroll
        for (int nj = 0; nj < 8; nj++) {
            int col = n0 + nj * 8 + 2 * c;
            if (rloc < nr) {
                __half2 h = __floats2half2_rn(acc[mi][nj][0] * s0, acc[mi][nj][1] * s0);
                *(__half2*)(Hout + (size_t)(row0 + rloc) * 128 + col) = h;
            }
            if (rloc + 8 < nr) {
                __half2 h = __floats2half2_rn(acc[mi][nj][2] * s1, acc[mi][nj][3] * s1);
                *(__half2*)(Hout + (size_t)(row0 + rloc + 8) * 128 + col) = h;
            }
        }
    }
}

// ---------------- aggregation: half-warp per node, LOCKSTEP halves --------
__global__ __launch_bounds__(256) void aggregate_k(const __half* __restrict__ H,
                                                   const float* __restrict__ bias,
                                                   __half* __restrict__ outp, int n,
                                                   int dopool) {
    __shared__ float pS[16][128];
    __shared__ float pM[16][128];
    int t = threadIdx.x;
    int hw = t >> 4;
    int lane16 = t & 15;
    int w = blockIdx.x * 16 + hw;
    unsigned hmask = 0xFFFFu << (t & 16);
    bool active = (w < n);

    int beg = 0, cnt = 0;
    if (active) {
        beg = d_rowstart[w];
        cnt = d_rowstart[w + 1] - beg;
    }
    int mc = cnt;
    int other = __shfl_xor_sync(0xffffffffu, cnt, 16);
    if (other > mc) mc = other;

    float acc[8];
#pragma unroll
    for (int q = 0; q < 8; q++) acc[q] = 0.f;
    const __half* Hl = H + lane16 * 8;

    for (int base = 0; base < mc; base += 16) {
        int wcnt = mc - base; if (wcnt > 16) wcnt = 16;
        int myrem = cnt - base;
        int idx = 0;
        if (lane16 < myrem) idx = d_csr[beg + base + lane16];
        uint4 h[4];
#pragma unroll
        for (int u = 0; u < 4; u++) {
            int s = __shfl_sync(hmask, idx, u, 16);
            h[u] = (u < myrem) ? *(const uint4*)(Hl + (size_t)s * 128)
                               : make_uint4(0u, 0u, 0u, 0u);
        }
        for (int j0 = 0; j0 < wcnt; j0 += 4) {
            uint4 h2[4];
#pragma unroll
            for (int u = 0; u < 4; u++) {
                int jj = j0 + 4 + u;
                int s = __shfl_sync(hmask, idx, jj & 15, 16);
                h2[u] = (jj < myrem && jj < 16) ? *(const uint4*)(Hl + (size_t)s * 128)
                                                : make_uint4(0u, 0u, 0u, 0u);
            }
#pragma unroll
            for (int u = 0; u < 4; u++) {
                const __half2* p2 = (const __half2*)&h[u];
#pragma unroll
                for (int q = 0; q < 4; q++) {
                    float2 f = __half22float2(p2[q]);
                    acc[2 * q]     += f.x;
                    acc[2 * q + 1] += f.y;
                }
            }
#pragma unroll
            for (int u = 0; u < 4; u++) h[u] = h2[u];
        }
    }

    float o[8];
#pragma unroll
    for (int q = 0; q < 8; q++) o[q] = 0.f;

    if (active) {
        uint4 hs = *(const uint4*)(Hl + (size_t)w * 128);
        const __half2* p2 = (const __half2*)&hs;
#pragma unroll
        for (int q = 0; q < 4; q++) {
            float2 f = __half22float2(p2[q]);
            acc[2 * q]     += f.x;
            acc[2 * q + 1] += f.y;
        }
        float di = d_dinv[w];
        float4 b0 = *(const float4*)(bias + lane16 * 8);
        float4 b1 = *(const float4*)(bias + lane16 * 8 + 4);
        o[0] = fmaxf(di * acc[0] + b0.x, 0.f);
        o[1] = fmaxf(di * acc[1] + b0.y, 0.f);
        o[2] = fmaxf(di * acc[2] + b0.z, 0.f);
        o[3] = fmaxf(di * acc[3] + b0.w, 0.f);
        o[4] = fmaxf(di * acc[4] + b1.x, 0.f);
        o[5] = fmaxf(di * acc[5] + b1.y, 0.f);
        o[6] = fmaxf(di * acc[6] + b1.z, 0.f);
        o[7] = fmaxf(di * acc[7] + b1.w, 0.f);
        __half2 ho[4];
#pragma unroll
        for (int q = 0; q < 4; q++) ho[q] = __floats2half2_rn(o[2 * q], o[2 * q + 1]);
        *(uint4*)(outp + (size_t)w * 128 + lane16 * 8) = *(uint4*)ho;
    }

    if (dopool) {
#pragma unroll
        for (int q = 0; q < 8; q++) {
            pS[hw][lane16 * 8 + q] = o[q];
            pM[hw][lane16 * 8 + q] = o[q];
        }
        __syncthreads();
        if (t < 128) {
            float s = 0.f, mx = 0.f;
#pragma unroll
            for (int u = 0; u < 16; u++) { s += pS[u][t]; mx = fmaxf(mx, pM[u][t]); }
            atomicAdd(&d_scr.poolsum[t], s);
            atomicMax(&d_scr.poolmax[t], __float_as_uint(mx));
        }
    }
}

// ---------------- argmax key helpers ----------------
__device__ __forceinline__ unsigned enc_f(float f) {
    unsigned u = __float_as_uint(f);
    return (u & 0x80000000u) ? ~u : (u | 0x80000000u);
}
__device__ __forceinline__ unsigned long long mkkey(float f, int j) {
    return ((unsigned long long)enc_f(f) << 32) | (unsigned long long)(0xFFFFFFFFu - (unsigned)j);
}

// ---------------- head GEMVs: 256 cols/block (fine-grained waves) ---------
__global__ __launch_bounds__(256) void gemv_heads_k(const float* __restrict__ n1W,
                                                    const float* __restrict__ n1b,
                                                    const float* __restrict__ g1,
                                                    const float* __restrict__ n2W,
                                                    const float* __restrict__ n2b,
                                                    int ncols, int hb, float inv_n) {
    __shared__ float p[256];
    __shared__ float red[256];
    __shared__ unsigned long long redk[256];
    int t = threadIdx.x;
    if (t < 128) p[t] = d_scr.poolsum[t] * inv_n;
    else         p[t] = __uint_as_float(d_scr.poolmax[t - 128]);
    __syncthreads();
    int second = blockIdx.x >= hb;
    int b = second ? blockIdx.x - hb : blockIdx.x;
    int j = b * 256 + t;                 // one column per thread
    bool valid = (j < ncols);
    float a = 0.f;
    if (valid) {
        const float* W = second ? n2W : n1W;
#pragma unroll 4
        for (int k = 0; k < 256; k++)
            a += p[k] * W[(size_t)k * ncols + j];
    }
    if (!second) {
        float z = 0.f;
        if (valid) {
            z = (a + n1b[j] + g1[j]) * INV_TAU;
            d_z1[j] = z;
        }
        float lm = valid ? z : -1e30f;
        red[t] = lm;
        __syncthreads();
        for (int s = 128; s > 0; s >>= 1) {
            if (t < s) red[t] = fmaxf(red[t], red[t + s]);
            __syncthreads();
        }
        float bm = red[0];
        __syncthreads();
        red[t] = valid ? expf(z - bm) : 0.f;
        redk[t] = valid ? mkkey(z, j) : 0ull;
        __syncthreads();
        for (int s = 128; s > 0; s >>= 1) {
            if (t < s) {
                red[t] += red[t + s];
                if (redk[t + s] > redk[t]) redk[t] = redk[t + s];
            }
            __syncthreads();
        }
        if (t == 0) {
            d_bm[0][b] = bm;
            d_bs[0][b] = red[0];
            d_bk[0][b] = redk[0];
        }
    } else {
        if (valid) d_l2[j] = a + n2b[j];
    }
}

// ---------------- merge block stats -> global M, S, argmax (nb <= 512) ----
__global__ void merge_k(int which, int nb) {
    __shared__ float sm[512];
    __shared__ float ss[512];
    __shared__ unsigned long long sk[512];
    int t = threadIdx.x;  // 512
    float m = (t < nb) ? d_bm[which][t] : -1e30f;
    sm[t] = m;
    __syncthreads();
    for (int s = 256; s > 0; s >>= 1) {
        if (t < s) sm[t] = fmaxf(sm[t], sm[t + s]);
        __syncthreads();
    }
    float M = sm[0];
    __syncthreads();
    float ls = (t < nb) ? d_bs[which][t] * expf(d_bm[which][t] - M) : 0.f;
    ss[t] = ls;
    sk[t] = (t < nb) ? d_bk[which][t] : 0ull;
    __syncthreads();
    for (int s = 256; s > 0; s >>= 1) {
        if (t < s) {
            ss[t] += ss[t + s];
            if (sk[t + s] > sk[t]) sk[t] = sk[t + s];
        }
        __syncthreads();
    }
    if (t == 0) {
        d_scr.zmax[which] = M;
        d_scr.S[which] = ss[0];
        int idx = (int)(0xFFFFFFFFu - (unsigned)(sk[0] & 0xFFFFFFFFull));
        d_scr.isel[which] = idx;
        if (which == 0) d_conn[idx] = 1;
    }
}

// ---------------- mask of nodes connected to i1 ----------------
__global__ void conn_k(const int* __restrict__ srcp, const int* __restrict__ dstp, int E) {
    int i1 = d_scr.isel[0];
    int e = blockIdx.x * blockDim.x + threadIdx.x;
    if (e < E) {
        int s = srcp[e], d = dstp[e];
        if (s == i1 || d == i1) { d_conn[s] = 1; d_conn[d] = 1; }
    }
}

// ---------------- fused A: [write n1_soft] || [z2 compute + block stats] ----
__global__ __launch_bounds__(256) void fused_a_k(const float* __restrict__ g2,
                                                 float* __restrict__ outp, int n, int WB) {
    __shared__ float red[256];
    __shared__ unsigned long long redk[256];
    int t = threadIdx.x;
    if ((int)blockIdx.x < WB) {
        float M = d_scr.zmax[0];
        float invS = 1.0f / d_scr.S[0];
        int j4 = blockIdx.x * 256 + t;
        int j = j4 * 4;
        if (j < n) {
            float4 z = *(const float4*)(d_z1 + j);
            float4 o;
            o.x = expf(z.x - M) * invS;
            o.y = expf(z.y - M) * invS;
            o.z = expf(z.z - M) * invS;
            o.w = expf(z.w - M) * invS;
            *(float4*)(outp + j) = o;
        }
        return;
    }
    int b = blockIdx.x - WB;
    int j4 = b * 256 + t;
    int j = j4 * 4;
    bool valid = (j < n);
    float4 z = make_float4(0.f, 0.f, 0.f, 0.f);
    if (valid) {
        float4 l = *(const float4*)(d_l2 + j);
        uchar4 cn = *(const uchar4*)(d_conn + j);
        float4 g = *(const float4*)(g2 + j);
        z.x = ((cn.x ? MASKV : l.x) + g.x) * INV_TAU;
        z.y = ((cn.y ? MASKV : l.y) + g.y) * INV_TAU;
        z.z = ((cn.z ? MASKV : l.z) + g.z) * INV_TAU;
        z.w = ((cn.w ? MASKV : l.w) + g.w) * INV_TAU;
        *(float4*)(d_z2 + j) = z;
    }
    float lm = valid ? fmaxf(fmaxf(z.x, z.y), fmaxf(z.z, z.w)) : -1e30f;
    red[t] = lm;
    __syncthreads();
    for (int s = 128; s > 0; s >>= 1) {
        if (t < s) red[t] = fmaxf(red[t], red[t + s]);
        __syncthreads();
    }
    float bm = red[0];
    __syncthreads();
    float ls = 0.f;
    if (valid) ls = expf(z.x - bm) + expf(z.y - bm) + expf(z.z - bm) + expf(z.w - bm);
    red[t] = ls;
    unsigned long long key = 0ull;
    if (valid) {
        key = mkkey(z.x, j);
        unsigned long long k1 = mkkey(z.y, j + 1); if (k1 > key) key = k1;
        unsigned long long k2 = mkkey(z.z, j + 2); if (k2 > key) key = k2;
        unsigned long long k3 = mkkey(z.w, j + 3); if (k3 > key) key = k3;
    }
    redk[t] = key;
    __syncthreads();
    for (int s = 128; s > 0; s >>= 1) {
        if (t < s) {
            red[t] += red[t + s];
            if (redk[t + s] > redk[t]) redk[t] = redk[t + s];
        }
        __syncthreads();
    }
    if (t == 0) {
        d_bm[1][b] = bm;
        d_bs[1][b] = red[0];
        d_bk[1][b] = redk[0];
    }
}

// ---------------- fused B: [esoft] || [write n2_soft] ----------------
__global__ __launch_bounds__(256) void fused_b_k(const __half* __restrict__ G,
                                                 const float* __restrict__ eW,
                                                 const float* __restrict__ eb,
                                                 const float* __restrict__ ge,
                                                 float* __restrict__ outp, int n) {
    int t = threadIdx.x;
    if (blockIdx.x == 0) {
        __shared__ float red3[3][128];
        int i1 = d_scr.isel[0];
        int i2 = d_scr.isel[1];
        if (t < 128) {
            float a = __half2float(G[(size_t)i1 * 128 + t]);
            float b = __half2float(G[(size_t)i2 * 128 + t]);
#pragma unroll
            for (int o = 0; o < 3; o++)
                red3[o][t] = a * eW[t * 3 + o] + b * eW[(128 + t) * 3 + o];
        }
        __syncthreads();
        for (int s = 64; s > 0; s >>= 1) {
            if (t < s) {
                red3[0][t] += red3[0][t + s];
                red3[1][t] += red3[1][t + s];
                red3[2][t] += red3[2][t + s];
            }
            __syncthreads();
        }
        if (t == 0) {
            float z0 = (red3[0][0] + eb[0] + ge[0]) * INV_TAU;
            float z1v = (red3[1][0] + eb[1] + ge[1]) * INV_TAU;
            float z2v = (red3[2][0] + eb[2] + ge[2]) * INV_TAU;
            float m = fmaxf(z0, fmaxf(z1v, z2v));
            float e0 = expf(z0 - m), e1 = expf(z1v - m), e2 = expf(z2v - m);
            float inv = 1.0f / (e0 + e1 + e2);
            outp[2 * n + 0] = e0 * inv;
            outp[2 * n + 1] = e1 * inv;
            outp[2 * n + 2] = e2 * inv;
            outp[2 * n + 3] = 1.0f;
        }
        return;
    }
    float M = d_scr.zmax[1];
    float invS = 1.0f / d_scr.S[1];
    int j4 = (blockIdx.x - 1) * 256 + t;
    int j = j4 * 4;
    if (j < n) {
        float4 z = *(const float4*)(d_z2 + j);
        float4 o;
        o.x = expf(z.x - M) * invS;
        o.y = expf(z.y - M) * invS;
        o.z = expf(z.z - M) * invS;
        o.w = expf(z.w - M) * invS;
        *(float4*)(outp + n + j) = o;
    }
}

// ---------------- launcher (single stream — graph-capture safe) ----------
extern "C" void kernel_launch(void* const* d_in, const int* in_sizes, int n_in,
                              void* d_out, int out_size) {
    const float* x   = (const float*)d_in[0];
    const int*   ei  = (const int*)  d_in[1];
    const float* W1  = (const float*)d_in[2];
    const float* b1  = (const float*)d_in[3];
    const float* W2  = (const float*)d_in[4];
    const float* b2  = (const float*)d_in[5];
    const float* W3  = (const float*)d_in[6];
    const float* b3  = (const float*)d_in[7];
    const float* n1W = (const float*)d_in[8];
    const float* n1b = (const float*)d_in[9];
    const float* n2W = (const float*)d_in[10];
    const float* n2b = (const float*)d_in[11];
    const float* eW  = (const float*)d_in[12];
    const float* eb  = (const float*)d_in[13];
    const float* g1  = (const float*)d_in[16];
    const float* g2  = (const float*)d_in[17];
    const float* ge  = (const float*)d_in[18];
    float* out = (float*)d_out;

    int n = in_sizes[0] / 128;
    int E = in_sizes[1] / 2;
    const int* srcp = ei;
    const int* dstp = ei + E;

    void *pc, *pconn, *pscr, *pH, *pP, *pQ;
    cudaGetSymbolAddress(&pc,    d_counts);
    cudaGetSymbolAddress(&pconn, d_conn);
    cudaGetSymbolAddress(&pscr,  d_scr);
    cudaGetSymbolAddress(&pH,    d_H);
    cudaGetSymbolAddress(&pP,    d_P);
    cudaGetSymbolAddress(&pQ,    d_Q);
    __half* H = (__half*)pH;
    __half* P = (__half*)pP;
    __half* Q = (__half*)pQ;

    const int GEMM_SMEM = GROWS * XS_H * 2 + 64 * BS_W * 4;  // 68608 B
    cudaFuncSetAttribute(gemm_f16_k, cudaFuncAttributeMaxDynamicSharedMemorySize, GEMM_SMEM);

    int eblocks = (E + 255) / 256;
    int nb = (n + 1023) / 1024;

    cudaMemsetAsync(pc, 0, (size_t)n * sizeof(int), 0);
    degcount_k<<<eblocks, 256>>>(dstp, E);
    scan1_k<<<nb, 1024>>>(n);
    scan2_k<<<1, 128>>>(nb, n);
    scan3_k<<<nb, 1024>>>(n);

    int gblocks = (n + GROWS - 1) / GROWS;
    int ablocks = (n + 15) / 16;

    gemm_f16_k<<<gblocks, 256, GEMM_SMEM>>>(P, x, 1, W1, H, n);  // fused fp32->fp16
    fill_csr_k<<<eblocks, 256>>>(srcp, dstp, E);

    cudaMemsetAsync(pscr, 0, sizeof(Scr), 0);
    aggregate_k<<<ablocks, 256>>>(H, b1, Q, n, 0);
    gemm_f16_k<<<gblocks, 256, GEMM_SMEM>>>(Q, 0, 0, W2, H, n);
    aggregate_k<<<ablocks, 256>>>(H, b2, P, n, 0);
    gemm_f16_k<<<gblocks, 256, GEMM_SMEM>>>(P, 0, 0, W3, H, n);
    aggregate_k<<<ablocks, 256>>>(H, b3, Q, n, 1);  // Q = gcn, pool fused

    cudaMemsetAsync(pconn, 0, (size_t)n, 0);
    int hb = (n + 255) / 256;                   // 391 blocks per head
    gemv_heads_k<<<2 * hb, 256>>>(n1W, n1b, g1, n2W, n2b, n, hb, 1.0f / (float)n);
    merge_k<<<1, 512>>>(0, hb);
    conn_k<<<eblocks, 256>>>(srcp, dstp, E);

    int WB = (n + 1023) / 1024;                  // 98
    fused_a_k<<<2 * WB, 256>>>(g2, out, n, WB);
    merge_k<<<1, 512>>>(1, WB);
    fused_b_k<<<WB + 1, 256>>>(Q, eW, eb, ge, out, n);
}

// round 16
// speedup vs baseline: 1.7275x; 1.0138x over previous
#include <cuda_runtime.h>
#include <cuda_bf16.h>
#include <cuda_fp16.h>

#define NMAX 100000
#define EMAX 1600000
#define MASKV (-1000000000.0f)
#define INV_TAU 2.0f

// ---------------- device scratch (static allocation only) ----------------
struct Scr {
    float poolsum[128];
    unsigned int poolmax[128];
    float zmax[2];
    float S[2];
    int isel[2];
};

__device__ __half d_H[NMAX * 128];   // GEMM output (pre-aggregation)
__device__ __half d_P[NMAX * 128];   // activation ping
__device__ __half d_Q[NMAX * 128];   // activation pong
__device__ int    d_counts[NMAX];
__device__ int    d_rowstart[NMAX + 1];
__device__ int    d_cursor[NMAX];
__device__ int    d_csr[EMAX];
__device__ float  d_dinv[NMAX];
__device__ float  d_z1[NMAX];
__device__ float  d_l2[NMAX];
__device__ float  d_z2[NMAX];
__device__ unsigned char d_conn[NMAX];
__device__ int    d_bsum[128];
__device__ int    d_boff[128];
__device__ float  d_bm[2][512];
__device__ float  d_bs[2][512];
__device__ unsigned long long d_bk[2][512];
__device__ Scr    d_scr;

// ---------------- CSR build ----------------
__global__ void degcount_k(const int* __restrict__ dstp, int E) {
    int e = blockIdx.x * blockDim.x + threadIdx.x;
    if (e < E) atomicAdd(&d_counts[dstp[e]], 1);
}

__global__ void scan1_k(int n) {
    __shared__ int sm[1024];
    int t = threadIdx.x;
    int i = blockIdx.x * 1024 + t;
    int v = (i < n) ? d_counts[i] : 0;
    sm[t] = v;
    __syncthreads();
    for (int s = 512; s > 0; s >>= 1) {
        if (t < s) sm[t] += sm[t + s];
        __syncthreads();
    }
    if (t == 0) d_bsum[blockIdx.x] = sm[0];
}

__global__ void scan2_k(int nb, int n) {
    __shared__ int sm[128];
    int t = threadIdx.x;
    int v = (t < nb) ? d_bsum[t] : 0;
    sm[t] = v;
    __syncthreads();
    for (int d = 1; d < 128; d <<= 1) {
        int add = (t >= d) ? sm[t - d] : 0;
        __syncthreads();
        sm[t] += add;
        __syncthreads();
    }
    if (t < nb) d_boff[t] = sm[t] - v;
    if (t == nb - 1) d_rowstart[n] = sm[t];
}

__global__ void scan3_k(int n) {
    __shared__ int sm[1024];
    int t = threadIdx.x;
    int i = blockIdx.x * 1024 + t;
    int v = (i < n) ? d_counts[i] : 0;
    sm[t] = v;
    __syncthreads();
    for (int d = 1; d < 1024; d <<= 1) {
        int add = (t >= d) ? sm[t - d] : 0;
        __syncthreads();
        sm[t] += add;
        __syncthreads();
    }
    if (i < n) {
        int excl = sm[t] - v + d_boff[blockIdx.x];
        d_rowstart[i] = excl;
        d_cursor[i]   = excl;
        d_dinv[i]     = rsqrtf((float)v + 1.0f);
    }
}

__global__ void fill_csr_k(const int* __restrict__ srcp, const int* __restrict__ dstp, int E) {
    int e = blockIdx.x * blockDim.x + threadIdx.x;
    if (e < E) {
        int d = dstp[e];
        int pos = atomicAdd(&d_cursor[d], 1);
        d_csr[pos] = srcp[e];
    }
}

// ---------------- fp16 tensor-core GEMM: Hout = fp16(dinv * (X @ W)) ------
#define XS_H 136
#define BS_W 132
#define GROWS 128

__device__ __forceinline__ void mma_f16(float* d,
                                        unsigned a0, unsigned a1, unsigned a2, unsigned a3,
                                        unsigned b0, unsigned b1) {
    asm volatile("mma.sync.aligned.m16n8k16.row.col.f32.f16.f16.f32 "
                 "{%0,%1,%2,%3}, {%4,%5,%6,%7}, {%8,%9}, {%0,%1,%2,%3};"
                 : "+f"(d[0]), "+f"(d[1]), "+f"(d[2]), "+f"(d[3])
                 : "r"(a0), "r"(a1), "r"(a2), "r"(a3), "r"(b0), "r"(b1));
}

__global__ __launch_bounds__(256) void gemm_f16_k(const __half* __restrict__ X,
                                                  const float* __restrict__ X32,
                                                  int xf32,
                                                  const float* __restrict__ W,
                                                  __half* __restrict__ Hout, int n) {
    extern __shared__ char shraw[];
    __half*  xs = (__half*)shraw;                        // GROWS x XS_H halfs
    __half2* bs = (__half2*)(shraw + GROWS * XS_H * 2);  // 64 x BS_W half2

    int t = threadIdx.x;
    int row0 = blockIdx.x * GROWS;
    int nr = n - row0; if (nr > GROWS) nr = GROWS;

    for (int i = t; i < 64 * 128; i += 256) {
        int k2 = i >> 7, nn = i & 127;
        float w0 = W[(size_t)(2 * k2) * 128 + nn];
        float w1 = W[(size_t)(2 * k2 + 1) * 128 + nn];
        bs[k2 * BS_W + nn] = __floats2half2_rn(w0, w1);
    }
    if (xf32) {
        for (int i = t; i < nr * 32; i += 256) {
            int rr = i >> 5, c4 = i & 31;
            float4 v = *(const float4*)(X32 + (size_t)(row0 + rr) * 128 + c4 * 4);
            __half2 a = __floats2half2_rn(v.x, v.y);
            __half2 b = __floats2half2_rn(v.z, v.w);
            *(uint2*)(xs + rr * XS_H + c4 * 4) = make_uint2(*(unsigned*)&a, *(unsigned*)&b);
        }
    } else {
        for (int i = t; i < nr * 16; i += 256) {
            int rr = i >> 4, c8 = i & 15;
            uint4 v = *(const uint4*)(X + (size_t)(row0 + rr) * 128 + c8 * 8);
            *(uint4*)(xs + rr * XS_H + c8 * 8) = v;
        }
    }
    __syncthreads();

    int lane = t & 31, wid = t >> 5;
    int wm = wid & 3, wn = wid >> 2;
    int m0 = wm * 32, n0 = wn * 64;
    int r = lane >> 2, c = lane & 3;

    float acc[2][8][4];
#pragma unroll
    for (int mi = 0; mi < 2; mi++)
#pragma unroll
        for (int nj = 0; nj < 8; nj++)
#pragma unroll
            for (int q = 0; q < 4; q++) acc[mi][nj][q] = 0.f;

#pragma unroll
    for (int k0 = 0; k0 < 8; k0++) {
        unsigned a[2][4];
#pragma unroll
        for (int mi = 0; mi < 2; mi++) {
            const __half* xb = xs + (m0 + mi * 16 + r) * XS_H + k0 * 16 + 2 * c;
            a[mi][0] = *(const unsigned*)(xb);
            a[mi][1] = *(const unsigned*)(xb + 8 * XS_H);
            a[mi][2] = *(const unsigned*)(xb + 8);
            a[mi][3] = *(const unsigned*)(xb + 8 * XS_H + 8);
        }
#pragma unroll
        for (int nj = 0; nj < 8; nj++) {
            const __half2* bb = bs + (k0 * 8 + c) * BS_W + n0 + nj * 8 + r;
            unsigned b0 = *(const unsigned*)(bb);
            unsigned b1 = *(const unsigned*)(bb + 4 * BS_W);
#pragma unroll
            for (int mi = 0; mi < 2; mi++)
                mma_f16(acc[mi][nj], a[mi][0], a[mi][1], a[mi][2], a[mi][3], b0, b1);
        }
    }

#pragma unroll
    for (int mi = 0; mi < 2; mi++) {
        int rloc = m0 + mi * 16 + r;
        float s0 = 0.f, s1 = 0.f;
        if (rloc < nr)     s0 = d_dinv[row0 + rloc];
        if (rloc + 8 < nr) s1 = d_dinv[row0 + rloc + 8];
#pragma unroll
        for (int nj = 0; nj < 8; nj++) {
            int col = n0 + nj * 8 + 2 * c;
            if (rloc < nr) {
                __half2 h = __floats2half2_rn(acc[mi][nj][0] * s0, acc[mi][nj][1] * s0);
                *(__half2*)(Hout + (size_t)(row0 + rloc) * 128 + col) = h;
            }
            if (rloc + 8 < nr) {
                __half2 h = __floats2half2_rn(acc[mi][nj][2] * s1, acc[mi][nj][3] * s1);
                *(__half2*)(Hout + (size_t)(row0 + rloc + 8) * 128 + col) = h;
            }
        }
    }
}

// ---------------- aggregation: half-warp per node, LOCKSTEP halves --------
__global__ __launch_bounds__(256) void aggregate_k(const __half* __restrict__ H,
                                                   const float* __restrict__ bias,
                                                   __half* __restrict__ outp, int n,
                                                   int dopool) {
    __shared__ float pS[16][128];
    __shared__ float pM[16][128];
    int t = threadIdx.x;
    int hw = t >> 4;
    int lane16 = t & 15;
    int w = blockIdx.x * 16 + hw;
    unsigned hmask = 0xFFFFu << (t & 16);
    bool active = (w < n);

    int beg = 0, cnt = 0;
    if (active) {
        beg = d_rowstart[w];
        cnt = d_rowstart[w + 1] - beg;
    }
    int mc = cnt;
    int other = __shfl_xor_sync(0xffffffffu, cnt, 16);
    if (other > mc) mc = other;

    float acc[8];
#pragma unroll
    for (int q = 0; q < 8; q++) acc[q] = 0.f;
    const __half* Hl = H + lane16 * 8;

    for (int base = 0; base < mc; base += 16) {
        int wcnt = mc - base; if (wcnt > 16) wcnt = 16;
        int myrem = cnt - base;
        int idx = 0;
        if (lane16 < myrem) idx = d_csr[beg + base + lane16];
        uint4 h[4];
#pragma unroll
        for (int u = 0; u < 4; u++) {
            int s = __shfl_sync(hmask, idx, u, 16);
            h[u] = (u < myrem) ? *(const uint4*)(Hl + (size_t)s * 128)
                               : make_uint4(0u, 0u, 0u, 0u);
        }
        for (int j0 = 0; j0 < wcnt; j0 += 4) {
            uint4 h2[4];
#pragma unroll
            for (int u = 0; u < 4; u++) {
                int jj = j0 + 4 + u;
                int s = __shfl_sync(hmask, idx, jj & 15, 16);
                h2[u] = (jj < myrem && jj < 16) ? *(const uint4*)(Hl + (size_t)s * 128)
                                                : make_uint4(0u, 0u, 0u, 0u);
            }
#pragma unroll
            for (int u = 0; u < 4; u++) {
                const __half2* p2 = (const __half2*)&h[u];
#pragma unroll
                for (int q = 0; q < 4; q++) {
                    float2 f = __half22float2(p2[q]);
                    acc[2 * q]     += f.x;
                    acc[2 * q + 1] += f.y;
                }
            }
#pragma unroll
            for (int u = 0; u < 4; u++) h[u] = h2[u];
        }
    }

    float o[8];
#pragma unroll
    for (int q = 0; q < 8; q++) o[q] = 0.f;

    if (active) {
        uint4 hs = *(const uint4*)(Hl + (size_t)w * 128);
        const __half2* p2 = (const __half2*)&hs;
#pragma unroll
        for (int q = 0; q < 4; q++) {
            float2 f = __half22float2(p2[q]);
            acc[2 * q]     += f.x;
            acc[2 * q + 1] += f.y;
        }
        float di = d_dinv[w];
        float4 b0 = *(const float4*)(bias + lane16 * 8);
        float4 b1 = *(const float4*)(bias + lane16 * 8 + 4);
        o[0] = fmaxf(di * acc[0] + b0.x, 0.f);
        o[1] = fmaxf(di * acc[1] + b0.y, 0.f);
        o[2] = fmaxf(di * acc[2] + b0.z, 0.f);
        o[3] = fmaxf(di * acc[3] + b0.w, 0.f);
        o[4] = fmaxf(di * acc[4] + b1.x, 0.f);
        o[5] = fmaxf(di * acc[5] + b1.y, 0.f);
        o[6] = fmaxf(di * acc[6] + b1.z, 0.f);
        o[7] = fmaxf(di * acc[7] + b1.w, 0.f);
        __half2 ho[4];
#pragma unroll
        for (int q = 0; q < 4; q++) ho[q] = __floats2half2_rn(o[2 * q], o[2 * q + 1]);
        *(uint4*)(outp + (size_t)w * 128 + lane16 * 8) = *(uint4*)ho;
    }

    if (dopool) {
#pragma unroll
        for (int q = 0; q < 8; q++) {
            pS[hw][lane16 * 8 + q] = o[q];
            pM[hw][lane16 * 8 + q] = o[q];
        }
        __syncthreads();
        if (t < 128) {
            float s = 0.f, mx = 0.f;
#pragma unroll
            for (int u = 0; u < 16; u++) { s += pS[u][t]; mx = fmaxf(mx, pM[u][t]); }
            atomicAdd(&d_scr.poolsum[t], s);
            atomicMax(&d_scr.poolmax[t], __float_as_uint(mx));
        }
    }
}

// ---------------- argmax key helpers ----------------
__device__ __forceinline__ unsigned enc_f(float f) {
    unsigned u = __float_as_uint(f);
    return (u & 0x80000000u) ? ~u : (u | 0x80000000u);
}
__device__ __forceinline__ unsigned long long mkkey(float f, int j) {
    return ((unsigned long long)enc_f(f) << 32) | (unsigned long long)(0xFFFFFFFFu - (unsigned)j);
}

// ---------------- head GEMVs: 256 cols/block, streaming W reads -----------
__global__ __launch_bounds__(256) void gemv_heads_k(const float* __restrict__ n1W,
                                                    const float* __restrict__ n1b,
                                                    const float* __restrict__ g1,
                                                    const float* __restrict__ n2W,
                                                    const float* __restrict__ n2b,
                                                    int ncols, int hb, float inv_n) {
    __shared__ float p[256];
    __shared__ float red[256];
    __shared__ unsigned long long redk[256];
    int t = threadIdx.x;
    if (t < 128) p[t] = d_scr.poolsum[t] * inv_n;
    else         p[t] = __uint_as_float(d_scr.poolmax[t - 128]);
    __syncthreads();
    int second = blockIdx.x >= hb;
    int b = second ? blockIdx.x - hb : blockIdx.x;
    int j = b * 256 + t;                 // one column per thread
    bool valid = (j < ncols);
    float a = 0.f;
    if (valid) {
        const float* W = second ? n2W : n1W;
#pragma unroll 4
        for (int k = 0; k < 256; k++)
            a += p[k] * __ldcs(W + (size_t)k * ncols + j);   // evict-first stream
    }
    if (!second) {
        float z = 0.f;
        if (valid) {
            z = (a + n1b[j] + g1[j]) * INV_TAU;
            d_z1[j] = z;
        }
        float lm = valid ? z : -1e30f;
        red[t] = lm;
        __syncthreads();
        for (int s = 128; s > 0; s >>= 1) {
            if (t < s) red[t] = fmaxf(red[t], red[t + s]);
            __syncthreads();
        }
        float bm = red[0];
        __syncthreads();
        red[t] = valid ? expf(z - bm) : 0.f;
        redk[t] = valid ? mkkey(z, j) : 0ull;
        __syncthreads();
        for (int s = 128; s > 0; s >>= 1) {
            if (t < s) {
                red[t] += red[t + s];
                if (redk[t + s] > redk[t]) redk[t] = redk[t + s];
            }
            __syncthreads();
        }
        if (t == 0) {
            d_bm[0][b] = bm;
            d_bs[0][b] = red[0];
            d_bk[0][b] = redk[0];
        }
    } else {
        if (valid) d_l2[j] = a + n2b[j];
    }
}

// ---------------- merge block stats -> global M, S, argmax (nb <= 512) ----
__global__ void merge_k(int which, int nb) {
    __shared__ float sm[512];
    __shared__ float ss[512];
    __shared__ unsigned long long sk[512];
    int t = threadIdx.x;  // 512
    float m = (t < nb) ? d_bm[which][t] : -1e30f;
    sm[t] = m;
    __syncthreads();
    for (int s = 256; s > 0; s >>= 1) {
        if (t < s) sm[t] = fmaxf(sm[t], sm[t + s]);
        __syncthreads();
    }
    float M = sm[0];
    __syncthreads();
    float ls = (t < nb) ? d_bs[which][t] * expf(d_bm[which][t] - M) : 0.f;
    ss[t] = ls;
    sk[t] = (t < nb) ? d_bk[which][t] : 0ull;
    __syncthreads();
    for (int s = 256; s > 0; s >>= 1) {
        if (t < s) {
            ss[t] += ss[t + s];
            if (sk[t + s] > sk[t]) sk[t] = sk[t + s];
        }
        __syncthreads();
    }
    if (t == 0) {
        d_scr.zmax[which] = M;
        d_scr.S[which] = ss[0];
        int idx = (int)(0xFFFFFFFFu - (unsigned)(sk[0] & 0xFFFFFFFFull));
        d_scr.isel[which] = idx;
        if (which == 0) d_conn[idx] = 1;
    }
}

// ---------------- mask of nodes connected to i1 ----------------
__global__ void conn_k(const int* __restrict__ srcp, const int* __restrict__ dstp, int E) {
    int i1 = d_scr.isel[0];
    int e = blockIdx.x * blockDim.x + threadIdx.x;
    if (e < E) {
        int s = srcp[e], d = dstp[e];
        if (s == i1 || d == i1) { d_conn[s] = 1; d_conn[d] = 1; }
    }
}

// ---------------- fused A: [write n1_soft] || [z2 compute + block stats] ----
// one element per thread; WB blocks for each half
__global__ __launch_bounds__(256) void fused_a_k(const float* __restrict__ g2,
                                                 float* __restrict__ outp, int n, int WB) {
    __shared__ float red[256];
    __shared__ unsigned long long redk[256];
    int t = threadIdx.x;
    if ((int)blockIdx.x < WB) {
        float M = d_scr.zmax[0];
        float invS = 1.0f / d_scr.S[0];
        int j = blockIdx.x * 256 + t;
        if (j < n) outp[j] = expf(d_z1[j] - M) * invS;
        return;
    }
    int b = blockIdx.x - WB;
    int j = b * 256 + t;
    bool valid = (j < n);
    float z = 0.f;
    if (valid) {
        float l = d_conn[j] ? MASKV : d_l2[j];
        z = (l + g2[j]) * INV_TAU;
        d_z2[j] = z;
    }
    red[t] = valid ? z : -1e30f;
    __syncthreads();
    for (int s = 128; s > 0; s >>= 1) {
        if (t < s) red[t] = fmaxf(red[t], red[t + s]);
        __syncthreads();
    }
    float bm = red[0];
    __syncthreads();
    red[t]  = valid ? expf(z - bm) : 0.f;
    redk[t] = valid ? mkkey(z, j) : 0ull;
    __syncthreads();
    for (int s = 128; s > 0; s >>= 1) {
        if (t < s) {
            red[t] += red[t + s];
            if (redk[t + s] > redk[t]) redk[t] = redk[t + s];
        }
        __syncthreads();
    }
    if (t == 0) {
        d_bm[1][b] = bm;
        d_bs[1][b] = red[0];
        d_bk[1][b] = redk[0];
    }
}

// ---------------- fused B: [esoft] || [write n2_soft] ----------------
__global__ __launch_bounds__(256) void fused_b_k(const __half* __restrict__ G,
                                                 const float* __restrict__ eW,
                                                 const float* __restrict__ eb,
                                                 const float* __restrict__ ge,
                                                 float* __restrict__ outp, int n) {
    int t = threadIdx.x;
    if (blockIdx.x == 0) {
        __shared__ float red3[3][128];
        int i1 = d_scr.isel[0];
        int i2 = d_scr.isel[1];
        if (t < 128) {
            float a = __half2float(G[(size_t)i1 * 128 + t]);
            float b = __half2float(G[(size_t)i2 * 128 + t]);
#pragma unroll
            for (int o = 0; o < 3; o++)
                red3[o][t] = a * eW[t * 3 + o] + b * eW[(128 + t) * 3 + o];
        }
        __syncthreads();
        for (int s = 64; s > 0; s >>= 1) {
            if (t < s) {
                red3[0][t] += red3[0][t + s];
                red3[1][t] += red3[1][t + s];
                red3[2][t] += red3[2][t + s];
            }
            __syncthreads();
        }
        if (t == 0) {
            float z0 = (red3[0][0] + eb[0] + ge[0]) * INV_TAU;
            float z1v = (red3[1][0] + eb[1] + ge[1]) * INV_TAU;
            float z2v = (red3[2][0] + eb[2] + ge[2]) * INV_TAU;
            float m = fmaxf(z0, fmaxf(z1v, z2v));
            float e0 = expf(z0 - m), e1 = expf(z1v - m), e2 = expf(z2v - m);
            float inv = 1.0f / (e0 + e1 + e2);
            outp[2 * n + 0] = e0 * inv;
            outp[2 * n + 1] = e1 * inv;
            outp[2 * n + 2] = e2 * inv;
            outp[2 * n + 3] = 1.0f;
        }
        return;
    }
    float M = d_scr.zmax[1];
    float invS = 1.0f / d_scr.S[1];
    int j = (blockIdx.x - 1) * 256 + t;
    if (j < n) outp[n + j] = expf(d_z2[j] - M) * invS;
}

// ---------------- launcher (single stream — graph-capture safe) ----------
extern "C" void kernel_launch(void* const* d_in, const int* in_sizes, int n_in,
                              void* d_out, int out_size) {
    const float* x   = (const float*)d_in[0];
    const int*   ei  = (const int*)  d_in[1];
    const float* W1  = (const float*)d_in[2];
    const float* b1  = (const float*)d_in[3];
    const float* W2  = (const float*)d_in[4];
    const float* b2  = (const float*)d_in[5];
    const float* W3  = (const float*)d_in[6];
    const float* b3  = (const float*)d_in[7];
    const float* n1W = (const float*)d_in[8];
    const float* n1b = (const float*)d_in[9];
    const float* n2W = (const float*)d_in[10];
    const float* n2b = (const float*)d_in[11];
    const float* eW  = (const float*)d_in[12];
    const float* eb  = (const float*)d_in[13];
    const float* g1  = (const float*)d_in[16];
    const float* g2  = (const float*)d_in[17];
    const float* ge  = (const float*)d_in[18];
    float* out = (float*)d_out;

    int n = in_sizes[0] / 128;
    int E = in_sizes[1] / 2;
    const int* srcp = ei;
    const int* dstp = ei + E;

    void *pc, *pconn, *pscr, *pH, *pP, *pQ;
    cudaGetSymbolAddress(&pc,    d_counts);
    cudaGetSymbolAddress(&pconn, d_conn);
    cudaGetSymbolAddress(&pscr,  d_scr);
    cudaGetSymbolAddress(&pH,    d_H);
    cudaGetSymbolAddress(&pP,    d_P);
    cudaGetSymbolAddress(&pQ,    d_Q);
    __half* H = (__half*)pH;
    __half* P = (__half*)pP;
    __half* Q = (__half*)pQ;

    const int GEMM_SMEM = GROWS * XS_H * 2 + 64 * BS_W * 4;  // 68608 B
    cudaFuncSetAttribute(gemm_f16_k, cudaFuncAttributeMaxDynamicSharedMemorySize, GEMM_SMEM);

    int eblocks = (E + 255) / 256;
    int nb = (n + 1023) / 1024;

    cudaMemsetAsync(pc, 0, (size_t)n * sizeof(int), 0);
    degcount_k<<<eblocks, 256>>>(dstp, E);
    scan1_k<<<nb, 1024>>>(n);
    scan2_k<<<1, 128>>>(nb, n);
    scan3_k<<<nb, 1024>>>(n);

    int gblocks = (n + GROWS - 1) / GROWS;
    int ablocks = (n + 15) / 16;

    gemm_f16_k<<<gblocks, 256, GEMM_SMEM>>>(P, x, 1, W1, H, n);  // fused fp32->fp16
    fill_csr_k<<<eblocks, 256>>>(srcp, dstp, E);

    cudaMemsetAsync(pscr, 0, sizeof(Scr), 0);
    aggregate_k<<<ablocks, 256>>>(H, b1, Q, n, 0);
    gemm_f16_k<<<gblocks, 256, GEMM_SMEM>>>(Q, 0, 0, W2, H, n);
    aggregate_k<<<ablocks, 256>>>(H, b2, P, n, 0);
    gemm_f16_k<<<gblocks, 256, GEMM_SMEM>>>(P, 0, 0, W3, H, n);
    aggregate_k<<<ablocks, 256>>>(H, b3, Q, n, 1);  // Q = gcn, pool fused

    cudaMemsetAsync(pconn, 0, (size_t)n, 0);
    int hb = (n + 255) / 256;                   // 391 blocks per head
    gemv_heads_k<<<2 * hb, 256>>>(n1W, n1b, g1, n2W, n2b, n, hb, 1.0f / (float)n);
    merge_k<<<1, 512>>>(0, hb);
    conn_k<<<eblocks, 256>>>(srcp, dstp, E);

    int WB = (n + 255) / 256;                   // 391 (one element/thread)
    fused_a_k<<<2 * WB, 256>>>(g2, out, n, WB);
    merge_k<<<1, 512>>>(1, WB);
    fused_b_k<<<WB + 1, 256>>>(Q, eW, eb, ge, out, n);
}